// round 2
// baseline (speedup 1.0000x reference)
#include <cuda_runtime.h>

// Problem constants
constexpr int Bc = 4;
constexpr int Mc = 128;
constexpr int Ec = 768;
constexpr int Rc = 768;
constexpr int Sc = Mc * (Mc + 1) / 2;   // 8256

// ---------------- device scratch (no allocations allowed) ----------------
__device__ float g_erow[Bc * Ec * Mc];     // [B][E][M]
__device__ float g_ecol[Bc * Ec * Mc];     // [B][E][M]
__device__ float g_rrow[Bc * Rc * Mc];     // [B][R][M]
__device__ float g_rcol[Bc * Rc * Mc];     // [B][R][M]
__device__ float g_mean_rel[Bc * Mc * Mc];
__device__ float g_rstd_rel[Bc * Mc * Mc];
__device__ float g_mean_ent[Bc * Sc];
__device__ float g_rstd_ent[Bc * Sc];
__device__ float g_alT[Mc * Ec];           // ent_alpha^T  [j][e]
__device__ float g_beT[Mc * Ec];           // ent_beta^T   [j][e]
__device__ float g_ralT[Mc * Rc];          // rel_alpha^T  [j][r]
__device__ float g_rbeT[Mc * Rc];          // rel_beta^T   [j][r]

// ---------------- mean / rstd per row of 768 ----------------
// which==0 -> rel rows (B*M*M), which==1 -> ent rows (B*S)
__global__ void k_meanvar(const float* __restrict__ x, int which) {
    int row = blockIdx.x;
    const float* p = x + (size_t)row * 768;
    float s = 0.f, ss = 0.f;
    for (int t = threadIdx.x; t < 768; t += 256) {
        float v = p[t];
        s += v;
        ss = fmaf(v, v, ss);
    }
    #pragma unroll
    for (int o = 16; o; o >>= 1) {
        s  += __shfl_xor_sync(0xffffffffu, s, o);
        ss += __shfl_xor_sync(0xffffffffu, ss, o);
    }
    __shared__ float sm[8], sm2[8];
    int w = threadIdx.x >> 5;
    if ((threadIdx.x & 31) == 0) { sm[w] = s; sm2[w] = ss; }
    __syncthreads();
    if (threadIdx.x == 0) {
        float S = 0.f, SS = 0.f;
        #pragma unroll
        for (int q = 0; q < 8; ++q) { S += sm[q]; SS += sm2[q]; }
        float mean = S * (1.f / 768.f);
        float var  = SS * (1.f / 768.f) - mean * mean;
        float d    = var + 1e-12f;
        float r    = 1.f / (d * d);           // faithful: std = (var+eps)^2
        if (which == 0) { g_mean_rel[row] = mean; g_rstd_rel[row] = r; }
        else            { g_mean_ent[row] = mean; g_rstd_ent[row] = r; }
    }
}

// ---------------- transpose the 4 small [dim][M] params to [M][dim] ----------------
__global__ void k_transpose4(const float* __restrict__ ea, const float* __restrict__ eb,
                             const float* __restrict__ ra, const float* __restrict__ rb) {
    int which = blockIdx.y;
    const float* in = (which == 0) ? ea : (which == 1) ? eb : (which == 2) ? ra : rb;
    float* out = (which == 0) ? g_alT : (which == 1) ? g_beT : (which == 2) ? g_ralT : g_rbeT;
    int idx = blockIdx.x * 256 + threadIdx.x;     // over 128*768
    if (idx < Mc * 768) {
        int j = idx / 768;
        int e = idx - j * 768;
        out[idx] = in[e * Mc + j];
    }
}

// ---------------- erow / ecol (mirror is symmetric in (i,j)) ----------------
__global__ void k_rowcol_ent(const float* __restrict__ eh, const int* __restrict__ mir) {
    int b = blockIdx.x >> 7, i = blockIdx.x & 127;
    __shared__ int mids[Mc];
    if (threadIdx.x < Mc) mids[threadIdx.x] = mir[i * Mc + threadIdx.x];
    __syncthreads();
    for (int e = threadIdx.x; e < Ec; e += 256) {
        float aR = 0.f, aC = 0.f;
        #pragma unroll 4
        for (int j = 0; j < Mc; ++j) {
            float v = eh[((size_t)b * Sc + mids[j]) * Ec + e];
            aR = fmaf(v, g_alT[j * Ec + e], aR);
            aC = fmaf(v, g_beT[j * Ec + e], aC);
        }
        g_erow[(b * Ec + e) * Mc + i] = aR;
        g_ecol[(b * Ec + e) * Mc + i] = aC;
    }
}

// ---------------- rrow / rcol from rel_guided ----------------
__global__ void k_rowcol_rel(const float* __restrict__ rg) {
    int b = blockIdx.x >> 7, k = blockIdx.x & 127;
    const float* rgb = rg + (size_t)b * Mc * Mc * Rc;
    for (int r = threadIdx.x; r < Rc; r += 256) {
        float aR = 0.f, aC = 0.f;
        const float* prow = rgb + (size_t)k * Mc * Rc + r;   // rg[b,k,j,r], step j*Rc
        const float* pcol = rgb + (size_t)k * Rc + r;        // rg[b,i,k,r], step i*Mc*Rc
        #pragma unroll 4
        for (int j = 0; j < Mc; ++j) {
            aR = fmaf(prow[(size_t)j * Rc], g_ralT[j * Rc + r], aR);
            aC = fmaf(pcol[(size_t)j * Mc * Rc], g_rbeT[j * Rc + r], aC);
        }
        g_rrow[(b * Rc + r) * Mc + k] = aR;
        g_rcol[(b * Rc + r) * Mc + k] = aC;
    }
}

// ---------------- Kernel B: per-(b,i) dual GEMM + CLN -> rel_guided ----------------
// out tile: [128 r x 64 j], dual accumulators for Wb and Wg. K = E = 768.
__global__ __launch_bounds__(256) void k_relguided(
    const float* __restrict__ Wb, const float* __restrict__ Wg,
    const float* __restrict__ ebeta, const float* __restrict__ egamma,
    const float* __restrict__ rel_hs, float* __restrict__ rel_out) {
    const int rt = blockIdx.x >> 1;        // 0..5
    const int jt = blockIdx.x & 1;         // 0..1
    const int b  = blockIdx.y >> 7;
    const int i  = blockIdx.y & 127;
    const int r0 = rt * 128, j0 = jt * 64;

    __shared__ float ASb[16][132];
    __shared__ float ASg[16][132];
    __shared__ float BSs[16][68];

    const int tid = threadIdx.x;
    const int tr = tid >> 4;               // 0..15 -> r_local = tr*8
    const int tc = tid & 15;               // 0..15 -> j_local = tc*4

    float accB[8][4] = {};
    float accG[8][4] = {};

    const float* erow_b = g_erow + (size_t)b * Ec * Mc;
    const float* ecol_b = g_ecol + (size_t)b * Ec * Mc;

    for (int e0 = 0; e0 < Ec; e0 += 16) {
        __syncthreads();
        // A tiles (Wb, Wg): [128 r x 16 e] -> AS[k][r]
        #pragma unroll
        for (int it = 0; it < 2; ++it) {
            int f4 = tid + it * 256;       // 0..511
            int rr = f4 >> 2;              // 0..127
            int c4 = f4 & 3;               // k = c4*4..c4*4+3
            float4 vb = *(const float4*)(Wb + (size_t)(r0 + rr) * Ec + e0 + c4 * 4);
            float4 vg = *(const float4*)(Wg + (size_t)(r0 + rr) * Ec + e0 + c4 * 4);
            ASb[c4 * 4 + 0][rr] = vb.x; ASb[c4 * 4 + 1][rr] = vb.y;
            ASb[c4 * 4 + 2][rr] = vb.z; ASb[c4 * 4 + 3][rr] = vb.w;
            ASg[c4 * 4 + 0][rr] = vg.x; ASg[c4 * 4 + 1][rr] = vg.y;
            ASg[c4 * 4 + 2][rr] = vg.z; ASg[c4 * 4 + 3][rr] = vg.w;
        }
        // B tile: Cs[k][j] = erow[b, e0+k, i] * ecol[b, e0+k, j0+j]
        {
            int k  = tid >> 4;             // 0..15
            int j4 = tid & 15;             // 0..15
            float a = erow_b[(e0 + k) * Mc + i];
            float4 c = *(const float4*)(ecol_b + (size_t)(e0 + k) * Mc + j0 + j4 * 4);
            float4 sc = make_float4(c.x * a, c.y * a, c.z * a, c.w * a);
            *(float4*)&BSs[k][j4 * 4] = sc;
        }
        __syncthreads();
        #pragma unroll
        for (int k = 0; k < 16; ++k) {
            float4 bj = *(const float4*)&BSs[k][tc * 4];
            float4 ab0 = *(const float4*)&ASb[k][tr * 8];
            float4 ab1 = *(const float4*)&ASb[k][tr * 8 + 4];
            float4 ag0 = *(const float4*)&ASg[k][tr * 8];
            float4 ag1 = *(const float4*)&ASg[k][tr * 8 + 4];
            float bv[4] = {bj.x, bj.y, bj.z, bj.w};
            float abv[8] = {ab0.x, ab0.y, ab0.z, ab0.w, ab1.x, ab1.y, ab1.z, ab1.w};
            float agv[8] = {ag0.x, ag0.y, ag0.z, ag0.w, ag1.x, ag1.y, ag1.z, ag1.w};
            #pragma unroll
            for (int m = 0; m < 8; ++m)
                #pragma unroll
                for (int n = 0; n < 4; ++n) {
                    accB[m][n] = fmaf(abv[m], bv[n], accB[m][n]);
                    accG[m][n] = fmaf(agv[m], bv[n], accG[m][n]);
                }
        }
    }

    // epilogue: rel_guided = (x-mean)*rstd*(Pg+gamma) + Pb + beta
    const size_t rowbase = ((size_t)(b * Mc + i) * Mc) * Rc;
    float mr[4], rs[4];
    #pragma unroll
    for (int n = 0; n < 4; ++n) {
        int j = j0 + tc * 4 + n;
        mr[n] = g_mean_rel[(b * Mc + i) * Mc + j];
        rs[n] = g_rstd_rel[(b * Mc + i) * Mc + j];
    }
    float bet[8], gam[8];
    #pragma unroll
    for (int m = 0; m < 8; ++m) {
        bet[m] = ebeta[r0 + tr * 8 + m];
        gam[m] = egamma[r0 + tr * 8 + m];
    }
    #pragma unroll
    for (int n = 0; n < 4; ++n) {
        int j = j0 + tc * 4 + n;
        size_t base = rowbase + (size_t)j * Rc + r0 + tr * 8;
        float4 x0 = *(const float4*)(rel_hs + base);
        float4 x1 = *(const float4*)(rel_hs + base + 4);
        float xs[8] = {x0.x, x0.y, x0.z, x0.w, x1.x, x1.y, x1.z, x1.w};
        float o[8];
        #pragma unroll
        for (int m = 0; m < 8; ++m)
            o[m] = (xs[m] - mr[n]) * rs[n] * (accG[m][n] + gam[m]) + accB[m][n] + bet[m];
        *(float4*)(rel_out + base)     = make_float4(o[0], o[1], o[2], o[3]);
        *(float4*)(rel_out + base + 4) = make_float4(o[4], o[5], o[6], o[7]);
    }
}

// ---------------- Kernel E: cond(on-the-fly) dual GEMM + CLN -> ent_guided ----------------
// out tile: [128 s x 64 e], K = R = 768.
__global__ __launch_bounds__(256) void k_entguided(
    const float* __restrict__ Wb, const float* __restrict__ Wg,
    const float* __restrict__ rbeta, const float* __restrict__ rgamma,
    const float* __restrict__ lam, const int* __restrict__ upper_ids,
    const float* __restrict__ ent_hs, float* __restrict__ ent_out) {
    const int e0 = blockIdx.x * 64;        // 0..11 tiles
    const int s0 = blockIdx.y * 128;       // 0..64 tiles (last partial)
    const int b  = blockIdx.z;

    __shared__ float WbS[16][68];
    __shared__ float WgS[16][68];
    __shared__ float condS[16][132];
    __shared__ float rrS[16][128];
    __shared__ float rcS[16][128];
    __shared__ float lamS[16];
    __shared__ int   iS[128], jS[128];
    __shared__ float mS[128], sS[128];

    const int tid = threadIdx.x;
    const int tr = tid >> 4;               // s_local = tr*8
    const int tc = tid & 15;               // e_local = tc*4

    if (tid < 128) {
        int gs = s0 + tid;
        if (gs < Sc) {
            int u = upper_ids[gs];
            iS[tid] = u >> 7;
            jS[tid] = u & 127;
            mS[tid] = g_mean_ent[b * Sc + gs];
            sS[tid] = g_rstd_ent[b * Sc + gs];
        } else {
            iS[tid] = 0; jS[tid] = 0; mS[tid] = 0.f; sS[tid] = 0.f;
        }
    }

    float accB[8][4] = {};
    float accG[8][4] = {};

    const float* rrow_b = g_rrow + (size_t)b * Rc * Mc;
    const float* rcol_b = g_rcol + (size_t)b * Rc * Mc;

    for (int rc0 = 0; rc0 < Rc; rc0 += 16) {
        __syncthreads();
        // W tiles: [64 e x 16 r] -> WS[k][e]
        {
            int e  = tid >> 2;             // 0..63
            int c4 = tid & 3;              // k = c4*4..+3
            float4 vb = *(const float4*)(Wb + (size_t)(e0 + e) * Rc + rc0 + c4 * 4);
            float4 vg = *(const float4*)(Wg + (size_t)(e0 + e) * Rc + rc0 + c4 * 4);
            WbS[c4 * 4 + 0][e] = vb.x; WbS[c4 * 4 + 1][e] = vb.y;
            WbS[c4 * 4 + 2][e] = vb.z; WbS[c4 * 4 + 3][e] = vb.w;
            WgS[c4 * 4 + 0][e] = vg.x; WgS[c4 * 4 + 1][e] = vg.y;
            WgS[c4 * 4 + 2][e] = vg.z; WgS[c4 * 4 + 3][e] = vg.w;
        }
        // rrow/rcol rows for this k-chunk
        #pragma unroll
        for (int it = 0; it < 2; ++it) {
            int f4 = tid + it * 256;       // 0..511
            int k  = f4 >> 5;              // 0..15
            int m4 = f4 & 31;              // col m4*4
            *(float4*)&rrS[k][m4 * 4] = *(const float4*)(rrow_b + (size_t)(rc0 + k) * Mc + m4 * 4);
            *(float4*)&rcS[k][m4 * 4] = *(const float4*)(rcol_b + (size_t)(rc0 + k) * Mc + m4 * 4);
        }
        if (tid < 16) lamS[tid] = lam[rc0 + tid];
        __syncthreads();
        // cond[k][s] = lam*rr[i]*rc[j] + (1-lam)*rr[j]*rc[i]
        #pragma unroll
        for (int q = 0; q < 8; ++q) {
            int idx = tid * 8 + q;         // 0..2047
            int k = idx >> 7, s = idx & 127;
            float l = lamS[k];
            float v = l * rrS[k][iS[s]] * rcS[k][jS[s]]
                    + (1.f - l) * rrS[k][jS[s]] * rcS[k][iS[s]];
            condS[k][s] = v;
        }
        __syncthreads();
        #pragma unroll
        for (int k = 0; k < 16; ++k) {
            float4 sa = *(const float4*)&condS[k][tr * 8];
            float4 sb = *(const float4*)&condS[k][tr * 8 + 4];
            float4 eb = *(const float4*)&WbS[k][tc * 4];
            float4 eg = *(const float4*)&WgS[k][tc * 4];
            float sv[8] = {sa.x, sa.y, sa.z, sa.w, sb.x, sb.y, sb.z, sb.w};
            float ebv[4] = {eb.x, eb.y, eb.z, eb.w};
            float egv[4] = {eg.x, eg.y, eg.z, eg.w};
            #pragma unroll
            for (int m = 0; m < 8; ++m)
                #pragma unroll
                for (int n = 0; n < 4; ++n) {
                    accB[m][n] = fmaf(sv[m], ebv[n], accB[m][n]);
                    accG[m][n] = fmaf(sv[m], egv[n], accG[m][n]);
                }
        }
    }

    // epilogue
    float bet[4], gam[4];
    #pragma unroll
    for (int n = 0; n < 4; ++n) {
        bet[n] = rbeta[e0 + tc * 4 + n];
        gam[n] = rgamma[e0 + tc * 4 + n];
    }
    #pragma unroll
    for (int m = 0; m < 8; ++m) {
        int sl = tr * 8 + m;
        int gs = s0 + sl;
        if (gs >= Sc) continue;
        size_t base = ((size_t)b * Sc + gs) * Ec + e0 + tc * 4;
        float4 x = *(const float4*)(ent_hs + base);
        float xm = mS[sl], xr = sS[sl];
        float xs[4] = {x.x, x.y, x.z, x.w};
        float o[4];
        #pragma unroll
        for (int n = 0; n < 4; ++n)
            o[n] = (xs[n] - xm) * xr * (accG[m][n] + gam[n]) + accB[m][n] + bet[n];
        *(float4*)(ent_out + base) = make_float4(o[0], o[1], o[2], o[3]);
    }
}

// ---------------- launch ----------------
extern "C" void kernel_launch(void* const* d_in, const int* in_sizes, int n_in,
                              void* d_out, int out_size) {
    const float* ent_hs    = (const float*)d_in[0];
    const float* rel_hs    = (const float*)d_in[1];
    const float* ent_alpha = (const float*)d_in[2];
    const float* ent_beta  = (const float*)d_in[3];
    const float* rel_alpha = (const float*)d_in[4];
    const float* rel_beta  = (const float*)d_in[5];
    const float* lam       = (const float*)d_in[6];
    const float* egr_Wb    = (const float*)d_in[7];
    const float* egr_Wg    = (const float*)d_in[8];
    const float* egr_beta  = (const float*)d_in[9];
    const float* egr_gamma = (const float*)d_in[10];
    const float* rge_Wb    = (const float*)d_in[11];
    const float* rge_Wg    = (const float*)d_in[12];
    const float* rge_beta  = (const float*)d_in[13];
    const float* rge_gamma = (const float*)d_in[14];
    const int*   mirror    = (const int*)d_in[15];
    const int*   upper     = (const int*)d_in[16];
    // d_in[17] = lower_ids, implied by (i,j) swap; unused.

    float* ent_out = (float*)d_out;                              // [B,S,E]
    float* rel_out = (float*)d_out + (size_t)Bc * Sc * Ec;       // [B,M,M,R]

    k_meanvar<<<Bc * Mc * Mc, 256>>>(rel_hs, 0);
    k_meanvar<<<Bc * Sc, 256>>>(ent_hs, 1);
    k_transpose4<<<dim3((Mc * 768 + 255) / 256, 4), 256>>>(ent_alpha, ent_beta, rel_alpha, rel_beta);
    k_rowcol_ent<<<Bc * Mc, 256>>>(ent_hs, mirror);
    k_relguided<<<dim3(12, Bc * Mc), 256>>>(egr_Wb, egr_Wg, egr_beta, egr_gamma, rel_hs, rel_out);
    k_rowcol_rel<<<Bc * Mc, 256>>>(rel_out);
    k_entguided<<<dim3(12, (Sc + 127) / 128, Bc), 256>>>(rge_Wb, rge_Wg, rge_beta, rge_gamma,
                                                         lam, upper, ent_hs, ent_out);
}

// round 3
// speedup vs baseline: 1.1972x; 1.1972x over previous
#include <cuda_runtime.h>

constexpr int Bc = 4;
constexpr int Mc = 128;
constexpr int Ec = 768;
constexpr int Rc = 768;
constexpr int Sc = Mc * (Mc + 1) / 2;   // 8256

typedef unsigned long long ull;

// ---------------- f32x2 packed-math helpers (SASS FFMA2 path) ----------------
__device__ __forceinline__ ull splat2(float v) {
    ull r; asm("mov.b64 %0, {%1, %1};" : "=l"(r) : "f"(v)); return r;
}
__device__ __forceinline__ void fma2(ull &d, ull a, ull b) {
    asm("fma.rn.f32x2 %0, %1, %2, %0;" : "+l"(d) : "l"(a), "l"(b));
}
__device__ __forceinline__ float2 unp2(ull v) {
    float2 r; asm("mov.b64 {%0, %1}, %2;" : "=f"(r.x), "=f"(r.y) : "l"(v)); return r;
}

// ---------------- device scratch ----------------
__device__ float g_erow[Bc * Ec * Mc];     // [B][E][M]
__device__ float g_ecol[Bc * Ec * Mc];
__device__ float g_rrow[Bc * Rc * Mc];     // [B][R][M]
__device__ float g_rcol[Bc * Rc * Mc];
__device__ float g_mean_rel[Bc * Mc * Mc];
__device__ float g_rstd_rel[Bc * Mc * Mc];
__device__ float g_mean_ent[Bc * Sc];
__device__ float g_rstd_ent[Bc * Sc];
__device__ float g_alT[Mc * Ec];
__device__ float g_beT[Mc * Ec];
__device__ float g_ralT[Mc * Rc];
__device__ float g_rbeT[Mc * Rc];
__device__ float g_cond[(size_t)Bc * Rc * Sc + 256];   // [B][R][S] (+pad for tile overread)

// ---------------- mean / rstd per row of 768 ----------------
__global__ void k_meanvar(const float* __restrict__ x, int which) {
    int row = blockIdx.x;
    const float* p = x + (size_t)row * 768;
    float s = 0.f, ss = 0.f;
    for (int t = threadIdx.x; t < 768; t += 256) {
        float v = p[t];
        s += v;
        ss = fmaf(v, v, ss);
    }
    #pragma unroll
    for (int o = 16; o; o >>= 1) {
        s  += __shfl_xor_sync(0xffffffffu, s, o);
        ss += __shfl_xor_sync(0xffffffffu, ss, o);
    }
    __shared__ float sm[8], sm2[8];
    int w = threadIdx.x >> 5;
    if ((threadIdx.x & 31) == 0) { sm[w] = s; sm2[w] = ss; }
    __syncthreads();
    if (threadIdx.x == 0) {
        float S = 0.f, SS = 0.f;
        #pragma unroll
        for (int q = 0; q < 8; ++q) { S += sm[q]; SS += sm2[q]; }
        float mean = S * (1.f / 768.f);
        float var  = SS * (1.f / 768.f) - mean * mean;
        float d    = var + 1e-12f;
        float r    = 1.f / (d * d);           // faithful: std = (var+eps)^2
        if (which == 0) { g_mean_rel[row] = mean; g_rstd_rel[row] = r; }
        else            { g_mean_ent[row] = mean; g_rstd_ent[row] = r; }
    }
}

// ---------------- transpose the 4 small [dim][M] params to [M][dim] ----------------
__global__ void k_transpose4(const float* __restrict__ ea, const float* __restrict__ eb,
                             const float* __restrict__ ra, const float* __restrict__ rb) {
    int which = blockIdx.y;
    const float* in = (which == 0) ? ea : (which == 1) ? eb : (which == 2) ? ra : rb;
    float* out = (which == 0) ? g_alT : (which == 1) ? g_beT : (which == 2) ? g_ralT : g_rbeT;
    int idx = blockIdx.x * 256 + threadIdx.x;
    if (idx < Mc * 768) {
        int j = idx / 768;
        int e = idx - j * 768;
        out[idx] = in[e * Mc + j];
    }
}

// ---------------- erow / ecol ----------------
__global__ void k_rowcol_ent(const float* __restrict__ eh, const int* __restrict__ mir) {
    int b = blockIdx.x >> 7, i = blockIdx.x & 127;
    __shared__ int mids[Mc];
    if (threadIdx.x < Mc) mids[threadIdx.x] = mir[i * Mc + threadIdx.x];
    __syncthreads();
    for (int e = threadIdx.x; e < Ec; e += 256) {
        float aR = 0.f, aC = 0.f;
        #pragma unroll 4
        for (int j = 0; j < Mc; ++j) {
            float v = eh[((size_t)b * Sc + mids[j]) * Ec + e];
            aR = fmaf(v, g_alT[j * Ec + e], aR);
            aC = fmaf(v, g_beT[j * Ec + e], aC);
        }
        g_erow[(b * Ec + e) * Mc + i] = aR;
        g_ecol[(b * Ec + e) * Mc + i] = aC;
    }
}

// ---------------- rrow / rcol from rel_guided ----------------
__global__ void k_rowcol_rel(const float* __restrict__ rg) {
    int b = blockIdx.x >> 7, k = blockIdx.x & 127;
    const float* rgb = rg + (size_t)b * Mc * Mc * Rc;
    for (int r = threadIdx.x; r < Rc; r += 256) {
        float aR = 0.f, aC = 0.f;
        const float* prow = rgb + (size_t)k * Mc * Rc + r;
        const float* pcol = rgb + (size_t)k * Rc + r;
        #pragma unroll 4
        for (int j = 0; j < Mc; ++j) {
            aR = fmaf(prow[(size_t)j * Rc], g_ralT[j * Rc + r], aR);
            aC = fmaf(pcol[(size_t)j * Mc * Rc], g_rbeT[j * Rc + r], aC);
        }
        g_rrow[(b * Rc + r) * Mc + k] = aR;
        g_rcol[(b * Rc + r) * Mc + k] = aC;
    }
}

// ---------------- precompute cond[b][r][s] ----------------
__global__ void k_cond(const float* __restrict__ lam, const int* __restrict__ upper) {
    int r = blockIdx.x, b = blockIdx.y;
    __shared__ float rr[128], rc[128];
    if (threadIdx.x < 128) {
        rr[threadIdx.x] = g_rrow[((size_t)b * Rc + r) * Mc + threadIdx.x];
        rc[threadIdx.x] = g_rcol[((size_t)b * Rc + r) * Mc + threadIdx.x];
    }
    __syncthreads();
    float l = lam[r];
    float* out = g_cond + ((size_t)b * Rc + r) * Sc;
    for (int s = threadIdx.x; s < Sc; s += 256) {
        int u = upper[s];
        int i = u >> 7, j = u & 127;
        out[s] = l * rr[i] * rc[j] + (1.f - l) * rr[j] * rc[i];
    }
}

// ================= Kernel B: per-(b,i) dual GEMM + CLN -> rel_guided =================
// Block tile [128 r x 128 j], thread tile 8x8, f32x2-packed along r. K = E = 768.
__global__ __launch_bounds__(256, 1) void k_relguided(
    const float* __restrict__ Wb, const float* __restrict__ Wg,
    const float* __restrict__ ebeta, const float* __restrict__ egamma,
    const float* __restrict__ rel_hs, float* __restrict__ rel_out) {
    const int r0 = blockIdx.x * 128;
    const int b  = blockIdx.y >> 7;
    const int i  = blockIdx.y & 127;

    __shared__ float ASb[16][132];
    __shared__ float ASg[16][132];
    __shared__ float BSs[16][132];

    const int tid = threadIdx.x;
    const int tr = tid >> 4;               // r_local = tr*8
    const int tc = tid & 15;               // j_local = tc*8

    ull accB2[4][8], accG2[4][8];
    #pragma unroll
    for (int q = 0; q < 4; ++q)
        #pragma unroll
        for (int n = 0; n < 8; ++n) { accB2[q][n] = 0ull; accG2[q][n] = 0ull; }

    const float* erow_b = g_erow + (size_t)b * Ec * Mc;
    const float* ecol_b = g_ecol + (size_t)b * Ec * Mc;

    // loader index precompute
    const int rr0 = tid >> 2,          c40 = (tid & 3) * 4;
    const int rr1 = (tid + 256) >> 2,  c41 = ((tid + 256) & 3) * 4;
    const int bk  = tid >> 4,          bj  = (tid & 15) * 4;

    float4 pvb0, pvb1, pvg0, pvg1, pc0, pc1;
    float pea;

#define REL_LOAD(E0) { \
    pvb0 = *(const float4*)(Wb + (size_t)(r0 + rr0) * Ec + (E0) + c40); \
    pvg0 = *(const float4*)(Wg + (size_t)(r0 + rr0) * Ec + (E0) + c40); \
    pvb1 = *(const float4*)(Wb + (size_t)(r0 + rr1) * Ec + (E0) + c41); \
    pvg1 = *(const float4*)(Wg + (size_t)(r0 + rr1) * Ec + (E0) + c41); \
    pea  = erow_b[(size_t)((E0) + bk) * Mc + i]; \
    pc0  = *(const float4*)(ecol_b + (size_t)((E0) + bk) * Mc + bj); \
    pc1  = *(const float4*)(ecol_b + (size_t)((E0) + bk) * Mc + bj + 64); }

#define REL_STORE() { \
    ASb[c40 + 0][rr0] = pvb0.x; ASb[c40 + 1][rr0] = pvb0.y; ASb[c40 + 2][rr0] = pvb0.z; ASb[c40 + 3][rr0] = pvb0.w; \
    ASg[c40 + 0][rr0] = pvg0.x; ASg[c40 + 1][rr0] = pvg0.y; ASg[c40 + 2][rr0] = pvg0.z; ASg[c40 + 3][rr0] = pvg0.w; \
    ASb[c41 + 0][rr1] = pvb1.x; ASb[c41 + 1][rr1] = pvb1.y; ASb[c41 + 2][rr1] = pvb1.z; ASb[c41 + 3][rr1] = pvb1.w; \
    ASg[c41 + 0][rr1] = pvg1.x; ASg[c41 + 1][rr1] = pvg1.y; ASg[c41 + 2][rr1] = pvg1.z; ASg[c41 + 3][rr1] = pvg1.w; \
    BSs[bk][bj + 0]  = pc0.x * pea; BSs[bk][bj + 1]  = pc0.y * pea; \
    BSs[bk][bj + 2]  = pc0.z * pea; BSs[bk][bj + 3]  = pc0.w * pea; \
    BSs[bk][bj + 64] = pc1.x * pea; BSs[bk][bj + 65] = pc1.y * pea; \
    BSs[bk][bj + 66] = pc1.z * pea; BSs[bk][bj + 67] = pc1.w * pea; }

    REL_LOAD(0);
    REL_STORE();
    __syncthreads();

    #pragma unroll 1
    for (int ch = 0; ch < 48; ++ch) {
        if (ch < 47) REL_LOAD((ch + 1) * 16);
        #pragma unroll
        for (int k = 0; k < 16; ++k) {
            ulonglong2 ab01 = *(const ulonglong2*)&ASb[k][tr * 8];
            ulonglong2 ab23 = *(const ulonglong2*)&ASb[k][tr * 8 + 4];
            ulonglong2 ag01 = *(const ulonglong2*)&ASg[k][tr * 8];
            ulonglong2 ag23 = *(const ulonglong2*)&ASg[k][tr * 8 + 4];
            float4 b0 = *(const float4*)&BSs[k][tc * 8];
            float4 b1 = *(const float4*)&BSs[k][tc * 8 + 4];
            ull ab[4] = {ab01.x, ab01.y, ab23.x, ab23.y};
            ull ag[4] = {ag01.x, ag01.y, ag23.x, ag23.y};
            ull sb[8] = {splat2(b0.x), splat2(b0.y), splat2(b0.z), splat2(b0.w),
                         splat2(b1.x), splat2(b1.y), splat2(b1.z), splat2(b1.w)};
            #pragma unroll
            for (int n = 0; n < 8; ++n)
                #pragma unroll
                for (int q = 0; q < 4; ++q) {
                    fma2(accB2[q][n], ab[q], sb[n]);
                    fma2(accG2[q][n], ag[q], sb[n]);
                }
        }
        __syncthreads();
        if (ch < 47) { REL_STORE(); __syncthreads(); }
    }

    // epilogue
    const size_t rowbase = ((size_t)(b * Mc + i) * Mc) * Rc;
    float bet[8], gam[8];
    #pragma unroll
    for (int m = 0; m < 8; ++m) {
        bet[m] = ebeta[r0 + tr * 8 + m];
        gam[m] = egamma[r0 + tr * 8 + m];
    }
    #pragma unroll
    for (int n = 0; n < 8; ++n) {
        int j = tc * 8 + n;
        float mr = g_mean_rel[(b * Mc + i) * Mc + j];
        float rs = g_rstd_rel[(b * Mc + i) * Mc + j];
        size_t base = rowbase + (size_t)j * Rc + r0 + tr * 8;
        float4 x0 = *(const float4*)(rel_hs + base);
        float4 x1 = *(const float4*)(rel_hs + base + 4);
        float xs[8] = {x0.x, x0.y, x0.z, x0.w, x1.x, x1.y, x1.z, x1.w};
        float o[8];
        #pragma unroll
        for (int q = 0; q < 4; ++q) {
            float2 pb = unp2(accB2[q][n]);
            float2 pg = unp2(accG2[q][n]);
            o[2 * q]     = (xs[2 * q]     - mr) * rs * (pg.x + gam[2 * q])     + pb.x + bet[2 * q];
            o[2 * q + 1] = (xs[2 * q + 1] - mr) * rs * (pg.y + gam[2 * q + 1]) + pb.y + bet[2 * q + 1];
        }
        *(float4*)(rel_out + base)     = make_float4(o[0], o[1], o[2], o[3]);
        *(float4*)(rel_out + base + 4) = make_float4(o[4], o[5], o[6], o[7]);
    }
#undef REL_LOAD
#undef REL_STORE
}

// ================= Kernel E: dual GEMM + CLN -> ent_guided =================
// Block tile [128 s x 128 e], thread tile 8x8, f32x2-packed along e. K = R = 768.
__global__ __launch_bounds__(256, 1) void k_entguided(
    const float* __restrict__ Wb, const float* __restrict__ Wg,
    const float* __restrict__ rbeta, const float* __restrict__ rgamma,
    const float* __restrict__ ent_hs, float* __restrict__ ent_out) {
    const int e0 = blockIdx.x * 128;
    const int s0 = blockIdx.y * 128;
    const int b  = blockIdx.z;

    __shared__ float WbS[16][132];
    __shared__ float WgS[16][132];
    __shared__ float CdS[16][132];
    __shared__ float mS[128], sS[128];

    const int tid = threadIdx.x;
    const int tr = tid >> 4;               // s_local = tr*8
    const int tc = tid & 15;               // e_local = tc*8

    if (tid < 128) {
        int gs = s0 + tid;
        if (gs < Sc) { mS[tid] = g_mean_ent[b * Sc + gs]; sS[tid] = g_rstd_ent[b * Sc + gs]; }
        else         { mS[tid] = 0.f; sS[tid] = 0.f; }
    }

    ull accB2[8][4], accG2[8][4];
    #pragma unroll
    for (int m = 0; m < 8; ++m)
        #pragma unroll
        for (int q = 0; q < 4; ++q) { accB2[m][q] = 0ull; accG2[m][q] = 0ull; }

    const float* condb = g_cond + (size_t)b * Rc * Sc;

    const int eL0 = tid >> 2,          wc0 = (tid & 3) * 4;
    const int eL1 = (tid + 256) >> 2,  wc1 = ((tid + 256) & 3) * 4;
    const int ck0 = tid >> 5,          cm0 = (tid & 31) * 4;
    const int ck1 = (tid + 256) >> 5,  cm1 = ((tid + 256) & 31) * 4;

    float4 qwb0, qwb1, qwg0, qwg1, qc0, qc1;

#define ENT_LOAD(RC0) { \
    qwb0 = *(const float4*)(Wb + (size_t)(e0 + eL0) * Rc + (RC0) + wc0); \
    qwg0 = *(const float4*)(Wg + (size_t)(e0 + eL0) * Rc + (RC0) + wc0); \
    qwb1 = *(const float4*)(Wb + (size_t)(e0 + eL1) * Rc + (RC0) + wc1); \
    qwg1 = *(const float4*)(Wg + (size_t)(e0 + eL1) * Rc + (RC0) + wc1); \
    qc0  = *(const float4*)(condb + (size_t)((RC0) + ck0) * Sc + s0 + cm0); \
    qc1  = *(const float4*)(condb + (size_t)((RC0) + ck1) * Sc + s0 + cm1); }

#define ENT_STORE() { \
    WbS[wc0 + 0][eL0] = qwb0.x; WbS[wc0 + 1][eL0] = qwb0.y; WbS[wc0 + 2][eL0] = qwb0.z; WbS[wc0 + 3][eL0] = qwb0.w; \
    WgS[wc0 + 0][eL0] = qwg0.x; WgS[wc0 + 1][eL0] = qwg0.y; WgS[wc0 + 2][eL0] = qwg0.z; WgS[wc0 + 3][eL0] = qwg0.w; \
    WbS[wc1 + 0][eL1] = qwb1.x; WbS[wc1 + 1][eL1] = qwb1.y; WbS[wc1 + 2][eL1] = qwb1.z; WbS[wc1 + 3][eL1] = qwb1.w; \
    WgS[wc1 + 0][eL1] = qwg1.x; WgS[wc1 + 1][eL1] = qwg1.y; WgS[wc1 + 2][eL1] = qwg1.z; WgS[wc1 + 3][eL1] = qwg1.w; \
    *(float4*)&CdS[ck0][cm0] = qc0; \
    *(float4*)&CdS[ck1][cm1] = qc1; }

    ENT_LOAD(0);
    ENT_STORE();
    __syncthreads();

    #pragma unroll 1
    for (int ch = 0; ch < 48; ++ch) {
        if (ch < 47) ENT_LOAD((ch + 1) * 16);
        #pragma unroll
        for (int k = 0; k < 16; ++k) {
            float4 c0 = *(const float4*)&CdS[k][tr * 8];
            float4 c1 = *(const float4*)&CdS[k][tr * 8 + 4];
            ulonglong2 wb01 = *(const ulonglong2*)&WbS[k][tc * 8];
            ulonglong2 wb23 = *(const ulonglong2*)&WbS[k][tc * 8 + 4];
            ulonglong2 wg01 = *(const ulonglong2*)&WgS[k][tc * 8];
            ulonglong2 wg23 = *(const ulonglong2*)&WgS[k][tc * 8 + 4];
            ull wb[4] = {wb01.x, wb01.y, wb23.x, wb23.y};
            ull wg[4] = {wg01.x, wg01.y, wg23.x, wg23.y};
            ull sc[8] = {splat2(c0.x), splat2(c0.y), splat2(c0.z), splat2(c0.w),
                         splat2(c1.x), splat2(c1.y), splat2(c1.z), splat2(c1.w)};
            #pragma unroll
            for (int m = 0; m < 8; ++m)
                #pragma unroll
                for (int q = 0; q < 4; ++q) {
                    fma2(accB2[m][q], sc[m], wb[q]);
                    fma2(accG2[m][q], sc[m], wg[q]);
                }
        }
        __syncthreads();
        if (ch < 47) { ENT_STORE(); __syncthreads(); }
    }

    // epilogue
    float bet[8], gam[8];
    #pragma unroll
    for (int n = 0; n < 8; ++n) {
        bet[n] = rbeta[e0 + tc * 8 + n];
        gam[n] = rgamma[e0 + tc * 8 + n];
    }
    #pragma unroll
    for (int m = 0; m < 8; ++m) {
        int sl = tr * 8 + m;
        int gs = s0 + sl;
        if (gs >= Sc) continue;
        size_t base = ((size_t)b * Sc + gs) * Ec + e0 + tc * 8;
        float4 x0 = *(const float4*)(ent_hs + base);
        float4 x1 = *(const float4*)(ent_hs + base + 4);
        float xs[8] = {x0.x, x0.y, x0.z, x0.w, x1.x, x1.y, x1.z, x1.w};
        float xm = mS[sl], xr = sS[sl];
        float o[8];
        #pragma unroll
        for (int q = 0; q < 4; ++q) {
            float2 ub = unp2(accB2[m][q]);
            float2 ug = unp2(accG2[m][q]);
            o[2 * q]     = (xs[2 * q]     - xm) * xr * (ug.x + gam[2 * q])     + ub.x + bet[2 * q];
            o[2 * q + 1] = (xs[2 * q + 1] - xm) * xr * (ug.y + gam[2 * q + 1]) + ub.y + bet[2 * q + 1];
        }
        *(float4*)(ent_out + base)     = make_float4(o[0], o[1], o[2], o[3]);
        *(float4*)(ent_out + base + 4) = make_float4(o[4], o[5], o[6], o[7]);
    }
#undef ENT_LOAD
#undef ENT_STORE
}

// ---------------- launch ----------------
extern "C" void kernel_launch(void* const* d_in, const int* in_sizes, int n_in,
                              void* d_out, int out_size) {
    const float* ent_hs    = (const float*)d_in[0];
    const float* rel_hs    = (const float*)d_in[1];
    const float* ent_alpha = (const float*)d_in[2];
    const float* ent_beta  = (const float*)d_in[3];
    const float* rel_alpha = (const float*)d_in[4];
    const float* rel_beta  = (const float*)d_in[5];
    const float* lam       = (const float*)d_in[6];
    const float* egr_Wb    = (const float*)d_in[7];
    const float* egr_Wg    = (const float*)d_in[8];
    const float* egr_beta  = (const float*)d_in[9];
    const float* egr_gamma = (const float*)d_in[10];
    const float* rge_Wb    = (const float*)d_in[11];
    const float* rge_Wg    = (const float*)d_in[12];
    const float* rge_beta  = (const float*)d_in[13];
    const float* rge_gamma = (const float*)d_in[14];
    const int*   mirror    = (const int*)d_in[15];
    const int*   upper     = (const int*)d_in[16];

    float* ent_out = (float*)d_out;                              // [B,S,E]
    float* rel_out = (float*)d_out + (size_t)Bc * Sc * Ec;       // [B,M,M,R]

    k_meanvar<<<Bc * Mc * Mc, 256>>>(rel_hs, 0);
    k_meanvar<<<Bc * Sc, 256>>>(ent_hs, 1);
    k_transpose4<<<dim3((Mc * 768 + 255) / 256, 4), 256>>>(ent_alpha, ent_beta, rel_alpha, rel_beta);
    k_rowcol_ent<<<Bc * Mc, 256>>>(ent_hs, mirror);
    k_relguided<<<dim3(6, Bc * Mc), 256>>>(egr_Wb, egr_Wg, egr_beta, egr_gamma, rel_hs, rel_out);
    k_rowcol_rel<<<Bc * Mc, 256>>>(rel_out);
    k_cond<<<dim3(Rc, Bc), 256>>>(lam, upper);
    k_entguided<<<dim3(6, (Sc + 127) / 128, Bc), 256>>>(rge_Wb, rge_Wg, rge_beta, rge_gamma,
                                                        ent_hs, ent_out);
}

// round 5
// speedup vs baseline: 2.0519x; 1.7139x over previous
#include <cuda_runtime.h>
#include <cuda_bf16.h>
#include <cstdint>

constexpr int Bc = 4;
constexpr int Mv = 128;
constexpr int Ev = 768;
constexpr int Rv = 768;
constexpr int Sv = Mv * (Mv + 1) / 2;   // 8256
constexpr int BSv = Bc * Sv;            // 33024

// ---------------- device scratch ----------------
__device__ float g_erow[Bc * Ev * Mv];     // [b][e][i]
__device__ float g_ecol[Bc * Ev * Mv];     // [b][e][j]
__device__ float g_rrow[Bc * Rv * Mv];
__device__ float g_rcol[Bc * Rv * Mv];
__device__ float g_mean_rel[Bc * Mv * Mv];
__device__ float g_rstd_rel[Bc * Mv * Mv];
__device__ float g_mean_ent[BSv];
__device__ float g_rstd_ent[BSv];
__device__ float g_alT[Mv * Ev];
__device__ float g_beT[Mv * Ev];
__device__ float g_ralT[Mv * Rv];
__device__ float g_rbeT[Mv * Rv];
__device__ float g_cond[(size_t)BSv * Rv];             // [(b,s)][r] fp32
__device__ __nv_bfloat16 g_W1hi[1536 * 768];           // rows 0..767 egr_Wb, 768..1535 egr_Wg
__device__ __nv_bfloat16 g_W1lo[1536 * 768];
__device__ __nv_bfloat16 g_W2hi[1536 * 768];           // rows 0..767 rge_Wb, 768..1535 rge_Wg
__device__ __nv_bfloat16 g_W2lo[1536 * 768];

// ---------------- PTX helpers (baseline-target only) ----------------
__device__ __forceinline__ uint32_t s2u(const void* p) {
    uint32_t a;
    asm("{ .reg .u64 t; cvta.to.shared.u64 t, %1; cvt.u32.u64 %0, t; }" : "=r"(a) : "l"(p));
    return a;
}
__device__ __forceinline__ void ldsm_x4(uint32_t r[4], uint32_t a) {
    asm volatile("ldmatrix.sync.aligned.m8n8.x4.shared.b16 {%0,%1,%2,%3}, [%4];"
        : "=r"(r[0]), "=r"(r[1]), "=r"(r[2]), "=r"(r[3]) : "r"(a));
}
__device__ __forceinline__ void ldsm_x2(uint32_t r[2], uint32_t a) {
    asm volatile("ldmatrix.sync.aligned.m8n8.x2.shared.b16 {%0,%1}, [%2];"
        : "=r"(r[0]), "=r"(r[1]) : "r"(a));
}
__device__ __forceinline__ void mma16816(float c[4], const uint32_t a[4], const uint32_t b[2]) {
    asm volatile("mma.sync.aligned.m16n8k16.row.col.f32.bf16.bf16.f32 "
        "{%0,%1,%2,%3}, {%4,%5,%6,%7}, {%8,%9}, {%0,%1,%2,%3};"
        : "+f"(c[0]), "+f"(c[1]), "+f"(c[2]), "+f"(c[3])
        : "r"(a[0]), "r"(a[1]), "r"(a[2]), "r"(a[3]), "r"(b[0]), "r"(b[1]));
}

// smem layout (bytes), padded stride 72 bf16 = 144B per row (conflict-free ldmatrix)
constexpr int A_HI = 0;
constexpr int A_LO = 18432;            // 128*144
constexpr int B_HI = 36864;
constexpr int B_LO = 73728;            // + 256*144
constexpr int DSMEM = 110592;

// ---------------- mean / rstd ----------------
__global__ void k_meanvar(const float* __restrict__ x, int which) {
    int row = blockIdx.x;
    const float* p = x + (size_t)row * 768;
    float s = 0.f, ss = 0.f;
    for (int t = threadIdx.x; t < 768; t += 256) {
        float v = p[t];
        s += v;
        ss = fmaf(v, v, ss);
    }
    #pragma unroll
    for (int o = 16; o; o >>= 1) {
        s  += __shfl_xor_sync(0xffffffffu, s, o);
        ss += __shfl_xor_sync(0xffffffffu, ss, o);
    }
    __shared__ float sm[8], sm2[8];
    int w = threadIdx.x >> 5;
    if ((threadIdx.x & 31) == 0) { sm[w] = s; sm2[w] = ss; }
    __syncthreads();
    if (threadIdx.x == 0) {
        float S = 0.f, SS = 0.f;
        #pragma unroll
        for (int q = 0; q < 8; ++q) { S += sm[q]; SS += sm2[q]; }
        float mean = S * (1.f / 768.f);
        float var  = SS * (1.f / 768.f) - mean * mean;
        float d    = var + 1e-12f;
        float r    = 1.f / (d * d);            // faithful: std = (var+eps)^2
        if (which == 0) { g_mean_rel[row] = mean; g_rstd_rel[row] = r; }
        else            { g_mean_ent[row] = mean; g_rstd_ent[row] = r; }
    }
}

// ---------------- transpose params ----------------
__global__ void k_transpose4(const float* __restrict__ ea, const float* __restrict__ eb,
                             const float* __restrict__ ra, const float* __restrict__ rb) {
    int which = blockIdx.y;
    const float* in = (which == 0) ? ea : (which == 1) ? eb : (which == 2) ? ra : rb;
    float* out = (which == 0) ? g_alT : (which == 1) ? g_beT : (which == 2) ? g_ralT : g_rbeT;
    int idx = blockIdx.x * 256 + threadIdx.x;
    if (idx < Mv * 768) {
        int j = idx / 768;
        int e = idx - j * 768;
        out[idx] = in[e * Mv + j];
    }
}

// ---------------- split weights into bf16 hi/lo ----------------
__global__ void k_splitw(const float* __restrict__ egWb, const float* __restrict__ egWg,
                         const float* __restrict__ rgWb, const float* __restrict__ rgWg) {
    int idx = blockIdx.x * 256 + threadIdx.x;
    if (idx >= 1536 * 768) return;
    int which = blockIdx.y;
    int row = idx / 768, col = idx - row * 768;
    const float* Wb = which ? rgWb : egWb;
    const float* Wg = which ? rgWg : egWg;
    float x = (row < 768) ? Wb[row * 768 + col] : Wg[(row - 768) * 768 + col];
    __nv_bfloat16 hi = __float2bfloat16(x);
    __nv_bfloat16 lo = __float2bfloat16(x - __bfloat162float(hi));
    if (which) { g_W2hi[idx] = hi; g_W2lo[idx] = lo; }
    else       { g_W1hi[idx] = hi; g_W1lo[idx] = lo; }
}

// ---------------- erow / ecol ----------------
__global__ void k_rowcol_ent(const float* __restrict__ eh, const int* __restrict__ mir) {
    int b = blockIdx.x >> 7, i = blockIdx.x & 127;
    __shared__ int mids[Mv];
    if (threadIdx.x < Mv) mids[threadIdx.x] = mir[i * Mv + threadIdx.x];
    __syncthreads();
    for (int e = threadIdx.x; e < Ev; e += 256) {
        float aR = 0.f, aC = 0.f;
        #pragma unroll 4
        for (int j = 0; j < Mv; ++j) {
            float v = eh[((size_t)b * Sv + mids[j]) * Ev + e];
            aR = fmaf(v, g_alT[j * Ev + e], aR);
            aC = fmaf(v, g_beT[j * Ev + e], aC);
        }
        g_erow[(b * Ev + e) * Mv + i] = aR;
        g_ecol[(b * Ev + e) * Mv + i] = aC;
    }
}

// ---------------- rrow / rcol from rel_guided ----------------
__global__ void k_rowcol_rel(const float* __restrict__ rg) {
    int b = blockIdx.x >> 7, k = blockIdx.x & 127;
    const float* rgb = rg + (size_t)b * Mv * Mv * Rv;
    for (int r = threadIdx.x; r < Rv; r += 256) {
        float aR = 0.f, aC = 0.f;
        const float* prow = rgb + (size_t)k * Mv * Rv + r;
        const float* pcol = rgb + (size_t)k * Rv + r;
        #pragma unroll 4
        for (int j = 0; j < Mv; ++j) {
            aR = fmaf(prow[(size_t)j * Rv], g_ralT[j * Rv + r], aR);
            aC = fmaf(pcol[(size_t)j * Mv * Rv], g_rbeT[j * Rv + r], aC);
        }
        g_rrow[(b * Rv + r) * Mv + k] = aR;
        g_rcol[(b * Rv + r) * Mv + k] = aC;
    }
}

// ---------------- cond[(b,s)][r] fp32 ----------------
__global__ void k_cond2(const float* __restrict__ lam, const int* __restrict__ upper) {
    int b = blockIdx.y;
    int s0 = blockIdx.x * 128;
    __shared__ float rrS[32][128], rcS[32][128], lamS[32];
    __shared__ int iS[128], jS[128];
    int tid = threadIdx.x;
    if (tid < 128) {
        int s = s0 + tid;
        if (s < Sv) { int u = upper[s]; iS[tid] = u >> 7; jS[tid] = u & 127; }
        else        { iS[tid] = 0; jS[tid] = 0; }
    }
    int s_loc = tid >> 1, rh = (tid & 1) * 16;
    int s = s0 + s_loc;
    for (int rch = 0; rch < 24; ++rch) {
        int r0 = rch * 32;
        __syncthreads();
        #pragma unroll
        for (int q = 0; q < 16; ++q) {
            int idx = q * 256 + tid;
            int rk = idx >> 7, mm = idx & 127;
            rrS[rk][mm] = g_rrow[((size_t)b * Rv + r0 + rk) * Mv + mm];
            rcS[rk][mm] = g_rcol[((size_t)b * Rv + r0 + rk) * Mv + mm];
        }
        if (tid < 32) lamS[tid] = lam[r0 + tid];
        __syncthreads();
        if (s < Sv) {
            int ii = iS[s_loc], jj = jS[s_loc];
            float out[16];
            #pragma unroll
            for (int rr = 0; rr < 16; ++rr) {
                int r = rh + rr;
                float l = lamS[r];
                out[rr] = l * rrS[r][ii] * rcS[r][jj] + (1.f - l) * rrS[r][jj] * rcS[r][ii];
            }
            float* dst = g_cond + ((size_t)b * Sv + s) * Rv + r0 + rh;
            #pragma unroll
            for (int q = 0; q < 4; ++q)
                *(float4*)(dst + q * 4) = make_float4(out[q * 4], out[q * 4 + 1], out[q * 4 + 2], out[q * 4 + 3]);
        }
    }
}

// ================= GEMM1: mma.sync bf16 3-pass -> rel_guided =================
// CTA: m=128 (j), n=256 (128 r x {Wb,Wg} interleaved), K=768 (e), chunks of 64.
__global__ __launch_bounds__(256, 1) void k_gemm1(
    const float* __restrict__ rel_hs, float* __restrict__ rel_out,
    const float* __restrict__ ebeta, const float* __restrict__ egam) {
    extern __shared__ char base[];
    const uint32_t sm0 = s2u(base);

    const int tid = threadIdx.x, w = tid >> 5, L = tid & 31;
    const int r0 = blockIdx.x * 128;
    const int byi = blockIdx.y;                // b*128 + i
    const int b = byi >> 7, i = byi & 127;
    const int m0w = (w >> 2) * 64, n0w = (w & 3) * 64;

    __shared__ float betS[128], gamS[128];
    if (tid < 128) { betS[tid] = ebeta[r0 + tid]; gamS[tid] = egam[r0 + tid]; }

    float acc[4][8][4];
    #pragma unroll
    for (int mt = 0; mt < 4; ++mt)
        #pragma unroll
        for (int nt = 0; nt < 8; ++nt)
            #pragma unroll
            for (int q = 0; q < 4; ++q) acc[mt][nt][q] = 0.f;

    const float* erow_bi = g_erow + (size_t)b * Ev * Mv + i;
    const float* ecol_b  = g_ecol + (size_t)b * Ev * Mv;

    const int jA = tid >> 1, khA = (tid & 1) * 32;
    const uint32_t aAddr = sm0 + (uint32_t)(m0w + (L & 15)) * 144 + (uint32_t)(L >> 4) * 16;
    const uint32_t bAddr = sm0 + B_HI + (uint32_t)(n0w + (L & 7)) * 144 + (uint32_t)((L >> 3) & 1) * 16;

    for (int ch = 0; ch < 12; ++ch) {
        const int k0 = ch * 64;
        __syncthreads();
        // A construct: A[j][k] = erow[k,i]*ecol[k,j] -> bf16 hi/lo
        {
            const float* pe = ecol_b + (size_t)(k0 + khA) * Mv + jA;
            const float* pr = erow_bi + (size_t)(k0 + khA) * Mv;
            char* Ah = base + (size_t)jA * 144 + khA * 2;
            char* Al = Ah + A_LO;
            #pragma unroll
            for (int g = 0; g < 4; ++g) {
                uint32_t hi[4], lo[4];
                #pragma unroll
                for (int p = 0; p < 4; ++p) {
                    int kk = g * 8 + p * 2;
                    float x0 = pe[(size_t)kk * Mv] * pr[(size_t)kk * Mv];
                    float x1 = pe[(size_t)(kk + 1) * Mv] * pr[(size_t)(kk + 1) * Mv];
                    __nv_bfloat162 h = __float22bfloat162_rn(make_float2(x0, x1));
                    float2 hf = __bfloat1622float2(h);
                    __nv_bfloat162 l = __float22bfloat162_rn(make_float2(x0 - hf.x, x1 - hf.y));
                    hi[p] = *(uint32_t*)&h; lo[p] = *(uint32_t*)&l;
                }
                *(uint4*)(Ah + g * 16) = make_uint4(hi[0], hi[1], hi[2], hi[3]);
                *(uint4*)(Al + g * 16) = make_uint4(lo[0], lo[1], lo[2], lo[3]);
            }
        }
        // B stage: 256 rows interleaved (even=Wb, odd=Wg), 64 k each
        #pragma unroll
        for (int q = 0; q < 8; ++q) {
            int u = q * 256 + tid;
            int row = u >> 3, seg = u & 7;
            int src = r0 + (row >> 1) + (row & 1) * 768;
            size_t go = (size_t)src * 768 + k0 + seg * 8;
            *(uint4*)(base + B_HI + row * 144 + seg * 16) = *(const uint4*)(g_W1hi + go);
            *(uint4*)(base + B_LO + row * 144 + seg * 16) = *(const uint4*)(g_W1lo + go);
        }
        __syncthreads();
        // compute: 4 k16-steps
        #pragma unroll
        for (int ks = 0; ks < 64; ks += 16) {
            uint32_t ah[4][4], al[4][4];
            #pragma unroll
            for (int mt = 0; mt < 4; ++mt) {
                ldsm_x4(ah[mt], aAddr + mt * 2304 + ks * 2);
                ldsm_x4(al[mt], aAddr + A_LO + mt * 2304 + ks * 2);
            }
            #pragma unroll
            for (int nt = 0; nt < 8; ++nt) {
                uint32_t bh[2], bl[2];
                ldsm_x2(bh, bAddr + nt * 1152 + ks * 2);
                ldsm_x2(bl, bAddr + (B_LO - B_HI) + nt * 1152 + ks * 2);
                #pragma unroll
                for (int mt = 0; mt < 4; ++mt) {
                    mma16816(acc[mt][nt], ah[mt], bh);
                    mma16816(acc[mt][nt], ah[mt], bl);
                    mma16816(acc[mt][nt], al[mt], bh);
                }
            }
        }
    }

    // epilogue: (c0,c1)/(c2,c3) = (proj_b, proj_g) for rows gid/gid+8
    const int gid = L >> 2, tig = L & 3;
    #pragma unroll
    for (int mt = 0; mt < 4; ++mt) {
        int j1 = m0w + mt * 16 + gid;
        int row1 = byi * 128 + j1, row2 = row1 + 8;
        float mn1 = g_mean_rel[row1], rs1 = g_rstd_rel[row1];
        float mn2 = g_mean_rel[row2], rs2 = g_rstd_rel[row2];
        const float* x1 = rel_hs + (size_t)row1 * 768;
        const float* x2 = rel_hs + (size_t)row2 * 768;
        float* o1 = rel_out + (size_t)row1 * 768;
        float* o2 = rel_out + (size_t)row2 * 768;
        #pragma unroll
        for (int nt = 0; nt < 8; ++nt) {
            int rl = (n0w >> 1) + nt * 4 + tig;
            int r = r0 + rl;
            const float* c = acc[mt][nt];
            o1[r] = (x1[r] - mn1) * rs1 * (c[1] + gamS[rl]) + c[0] + betS[rl];
            o2[r] = (x2[r] - mn2) * rs2 * (c[3] + gamS[rl]) + c[2] + betS[rl];
        }
    }
}

// ================= GEMM2: mma.sync bf16 3-pass -> ent_guided =================
// CTA: m=128 ((b,s) rows), n=256 (128 e x {Wb,Wg} interleaved), K=768 (r).
__global__ __launch_bounds__(256, 1) void k_gemm2(
    const float* __restrict__ ent_hs, float* __restrict__ ent_out,
    const float* __restrict__ rbeta, const float* __restrict__ rgam) {
    extern __shared__ char base[];
    const uint32_t sm0 = s2u(base);

    const int tid = threadIdx.x, w = tid >> 5, L = tid & 31;
    const int e0 = blockIdx.x * 128;
    const int m0 = blockIdx.y * 128;
    const int m0w = (w >> 2) * 64, n0w = (w & 3) * 64;

    __shared__ float betS[128], gamS[128];
    if (tid < 128) { betS[tid] = rbeta[e0 + tid]; gamS[tid] = rgam[e0 + tid]; }

    float acc[4][8][4];
    #pragma unroll
    for (int mt = 0; mt < 4; ++mt)
        #pragma unroll
        for (int nt = 0; nt < 8; ++nt)
            #pragma unroll
            for (int q = 0; q < 4; ++q) acc[mt][nt][q] = 0.f;

    const int mA = tid >> 1, khA = (tid & 1) * 32;
    const uint32_t aAddr = sm0 + (uint32_t)(m0w + (L & 15)) * 144 + (uint32_t)(L >> 4) * 16;
    const uint32_t bAddr = sm0 + B_HI + (uint32_t)(n0w + (L & 7)) * 144 + (uint32_t)((L >> 3) & 1) * 16;

    for (int ch = 0; ch < 12; ++ch) {
        const int k0 = ch * 64;
        __syncthreads();
        // A construct from g_cond rows
        {
            const float* src = g_cond + (size_t)(m0 + mA) * Rv + k0 + khA;
            char* Ah = base + (size_t)mA * 144 + khA * 2;
            char* Al = Ah + A_LO;
            #pragma unroll
            for (int g = 0; g < 4; ++g) {
                float4 f0 = *(const float4*)(src + g * 8);
                float4 f1 = *(const float4*)(src + g * 8 + 4);
                float xa[8] = {f0.x, f0.y, f0.z, f0.w, f1.x, f1.y, f1.z, f1.w};
                uint32_t hi[4], lo[4];
                #pragma unroll
                for (int p = 0; p < 4; ++p) {
                    __nv_bfloat162 h = __float22bfloat162_rn(make_float2(xa[p * 2], xa[p * 2 + 1]));
                    float2 hf = __bfloat1622float2(h);
                    __nv_bfloat162 l = __float22bfloat162_rn(make_float2(xa[p * 2] - hf.x, xa[p * 2 + 1] - hf.y));
                    hi[p] = *(uint32_t*)&h; lo[p] = *(uint32_t*)&l;
                }
                *(uint4*)(Ah + g * 16) = make_uint4(hi[0], hi[1], hi[2], hi[3]);
                *(uint4*)(Al + g * 16) = make_uint4(lo[0], lo[1], lo[2], lo[3]);
            }
        }
        // B stage
        #pragma unroll
        for (int q = 0; q < 8; ++q) {
            int u = q * 256 + tid;
            int row = u >> 3, seg = u & 7;
            int src = e0 + (row >> 1) + (row & 1) * 768;
            size_t go = (size_t)src * 768 + k0 + seg * 8;
            *(uint4*)(base + B_HI + row * 144 + seg * 16) = *(const uint4*)(g_W2hi + go);
            *(uint4*)(base + B_LO + row * 144 + seg * 16) = *(const uint4*)(g_W2lo + go);
        }
        __syncthreads();
        #pragma unroll
        for (int ks = 0; ks < 64; ks += 16) {
            uint32_t ah[4][4], al[4][4];
            #pragma unroll
            for (int mt = 0; mt < 4; ++mt) {
                ldsm_x4(ah[mt], aAddr + mt * 2304 + ks * 2);
                ldsm_x4(al[mt], aAddr + A_LO + mt * 2304 + ks * 2);
            }
            #pragma unroll
            for (int nt = 0; nt < 8; ++nt) {
                uint32_t bh[2], bl[2];
                ldsm_x2(bh, bAddr + nt * 1152 + ks * 2);
                ldsm_x2(bl, bAddr + (B_LO - B_HI) + nt * 1152 + ks * 2);
                #pragma unroll
                for (int mt = 0; mt < 4; ++mt) {
                    mma16816(acc[mt][nt], ah[mt], bh);
                    mma16816(acc[mt][nt], ah[mt], bl);
                    mma16816(acc[mt][nt], al[mt], bh);
                }
            }
        }
    }

    const int gid = L >> 2, tig = L & 3;
    #pragma unroll
    for (int mt = 0; mt < 4; ++mt) {
        int row1 = m0 + m0w + mt * 16 + gid, row2 = row1 + 8;
        float mn1 = g_mean_ent[row1], rs1 = g_rstd_ent[row1];
        float mn2 = g_mean_ent[row2], rs2 = g_rstd_ent[row2];
        const float* x1 = ent_hs + (size_t)row1 * 768;
        const float* x2 = ent_hs + (size_t)row2 * 768;
        float* o1 = ent_out + (size_t)row1 * 768;
        float* o2 = ent_out + (size_t)row2 * 768;
        #pragma unroll
        for (int nt = 0; nt < 8; ++nt) {
            int el = (n0w >> 1) + nt * 4 + tig;
            int e = e0 + el;
            const float* c = acc[mt][nt];
            o1[e] = (x1[e] - mn1) * rs1 * (c[1] + gamS[el]) + c[0] + betS[el];
            o2[e] = (x2[e] - mn2) * rs2 * (c[3] + gamS[el]) + c[2] + betS[el];
        }
    }
}

// ---------------- launch ----------------
extern "C" void kernel_launch(void* const* d_in, const int* in_sizes, int n_in,
                              void* d_out, int out_size) {
    const float* ent_hs    = (const float*)d_in[0];
    const float* rel_hs    = (const float*)d_in[1];
    const float* ent_alpha = (const float*)d_in[2];
    const float* ent_beta  = (const float*)d_in[3];
    const float* rel_alpha = (const float*)d_in[4];
    const float* rel_beta  = (const float*)d_in[5];
    const float* lam       = (const float*)d_in[6];
    const float* egr_Wb    = (const float*)d_in[7];
    const float* egr_Wg    = (const float*)d_in[8];
    const float* egr_beta  = (const float*)d_in[9];
    const float* egr_gamma = (const float*)d_in[10];
    const float* rge_Wb    = (const float*)d_in[11];
    const float* rge_Wg    = (const float*)d_in[12];
    const float* rge_beta  = (const float*)d_in[13];
    const float* rge_gamma = (const float*)d_in[14];
    const int*   mirror    = (const int*)d_in[15];
    const int*   upper     = (const int*)d_in[16];

    float* ent_out = (float*)d_out;                              // [B,S,E]
    float* rel_out = (float*)d_out + (size_t)Bc * Sv * Ev;       // [B,M,M,R]

    cudaFuncSetAttribute(k_gemm1, cudaFuncAttributeMaxDynamicSharedMemorySize, DSMEM);
    cudaFuncSetAttribute(k_gemm2, cudaFuncAttributeMaxDynamicSharedMemorySize, DSMEM);

    k_meanvar<<<Bc * Mv * Mv, 256>>>(rel_hs, 0);
    k_meanvar<<<BSv, 256>>>(ent_hs, 1);
    k_transpose4<<<dim3((Mv * 768 + 255) / 256, 4), 256>>>(ent_alpha, ent_beta, rel_alpha, rel_beta);
    k_splitw<<<dim3((1536 * 768 + 255) / 256, 2), 256>>>(egr_Wb, egr_Wg, rge_Wb, rge_Wg);
    k_rowcol_ent<<<Bc * Mv, 256>>>(ent_hs, mirror);
    k_gemm1<<<dim3(6, Bc * Mv), 256, DSMEM>>>(rel_hs, rel_out, egr_beta, egr_gamma);
    k_rowcol_rel<<<Bc * Mv, 256>>>(rel_out);
    k_cond2<<<dim3((Sv + 127) / 128, Bc), 256>>>(lam, upper);
    k_gemm2<<<dim3(6, BSv / 128), 256, DSMEM>>>(ent_hs, ent_out, rge_beta, rge_gamma);
}

// round 6
// speedup vs baseline: 2.2611x; 1.1020x over previous
#include <cuda_runtime.h>
#include <cuda_bf16.h>
#include <cstdint>

constexpr int Bc = 4;
constexpr int Mv = 128;
constexpr int Ev = 768;
constexpr int Rv = 768;
constexpr int Sv = Mv * (Mv + 1) / 2;   // 8256
constexpr int BSv = Bc * Sv;            // 33024

// ---------------- device scratch ----------------
__device__ float g_erow[Bc * Ev * Mv];     // [b][e][i]
__device__ float g_ecol[Bc * Ev * Mv];     // [b][e][j]
__device__ float g_rrow[Bc * Rv * Mv];
__device__ float g_rcol[Bc * Rv * Mv];
__device__ float g_mean_rel[Bc * Mv * Mv];
__device__ float g_rstd_rel[Bc * Mv * Mv];
__device__ float g_mean_ent[BSv];
__device__ float g_rstd_ent[BSv];
__device__ float g_alT[Mv * Ev];
__device__ float g_beT[Mv * Ev];
__device__ float g_ralT[Mv * Rv];
__device__ float g_rbeT[Mv * Rv];
__device__ __nv_bfloat16 g_cDhi[(size_t)BSv * Rv];     // cond split hi
__device__ __nv_bfloat16 g_cDlo[(size_t)BSv * Rv];     // cond split lo
__device__ __nv_bfloat16 g_W1hi[1536 * 768];           // rows 0..767 egr_Wb, 768..1535 egr_Wg
__device__ __nv_bfloat16 g_W1lo[1536 * 768];
__device__ __nv_bfloat16 g_W2hi[1536 * 768];           // rows 0..767 rge_Wb, 768..1535 rge_Wg
__device__ __nv_bfloat16 g_W2lo[1536 * 768];

// ---------------- PTX helpers (baseline-target only) ----------------
__device__ __forceinline__ uint32_t s2u(const void* p) {
    uint32_t a;
    asm("{ .reg .u64 t; cvta.to.shared.u64 t, %1; cvt.u32.u64 %0, t; }" : "=r"(a) : "l"(p));
    return a;
}
__device__ __forceinline__ void ldsm_x4(uint32_t r[4], uint32_t a) {
    asm volatile("ldmatrix.sync.aligned.m8n8.x4.shared.b16 {%0,%1,%2,%3}, [%4];"
        : "=r"(r[0]), "=r"(r[1]), "=r"(r[2]), "=r"(r[3]) : "r"(a));
}
__device__ __forceinline__ void ldsm_x2(uint32_t r[2], uint32_t a) {
    asm volatile("ldmatrix.sync.aligned.m8n8.x2.shared.b16 {%0,%1}, [%2];"
        : "=r"(r[0]), "=r"(r[1]) : "r"(a));
}
__device__ __forceinline__ void mma16816(float c[4], const uint32_t a[4], const uint32_t b[2]) {
    asm volatile("mma.sync.aligned.m16n8k16.row.col.f32.bf16.bf16.f32 "
        "{%0,%1,%2,%3}, {%4,%5,%6,%7}, {%8,%9}, {%0,%1,%2,%3};"
        : "+f"(c[0]), "+f"(c[1]), "+f"(c[2]), "+f"(c[3])
        : "r"(a[0]), "r"(a[1]), "r"(a[2]), "r"(a[3]), "r"(b[0]), "r"(b[1]));
}
__device__ __forceinline__ void cpa16(uint32_t dst, const void* src) {
    asm volatile("cp.async.cg.shared.global [%0], [%1], 16;" :: "r"(dst), "l"(src));
}
#define CP_COMMIT() asm volatile("cp.async.commit_group;" ::: "memory")
#define CP_WAIT0()  asm volatile("cp.async.wait_group 0;" ::: "memory")

// smem stage layout (bytes), padded stride 72 bf16 = 144B (conflict-free ldmatrix)
constexpr int A_LO = 18432;            // 128*144
constexpr int B_HI = 36864;
constexpr int B_LO = 73728;
constexpr int STGSZ = 110592;          // one stage
constexpr int DSMEM = 2 * STGSZ;       // 221184 B

// ---------------- mean / rstd ----------------
__global__ void k_meanvar(const float* __restrict__ x, int which) {
    int row = blockIdx.x;
    const float* p = x + (size_t)row * 768;
    float s = 0.f, ss = 0.f;
    for (int t = threadIdx.x; t < 768; t += 256) {
        float v = p[t];
        s += v;
        ss = fmaf(v, v, ss);
    }
    #pragma unroll
    for (int o = 16; o; o >>= 1) {
        s  += __shfl_xor_sync(0xffffffffu, s, o);
        ss += __shfl_xor_sync(0xffffffffu, ss, o);
    }
    __shared__ float sm[8], sm2[8];
    int w = threadIdx.x >> 5;
    if ((threadIdx.x & 31) == 0) { sm[w] = s; sm2[w] = ss; }
    __syncthreads();
    if (threadIdx.x == 0) {
        float S = 0.f, SS = 0.f;
        #pragma unroll
        for (int q = 0; q < 8; ++q) { S += sm[q]; SS += sm2[q]; }
        float mean = S * (1.f / 768.f);
        float var  = SS * (1.f / 768.f) - mean * mean;
        float d    = var + 1e-12f;
        float r    = 1.f / (d * d);            // faithful: std = (var+eps)^2
        if (which == 0) { g_mean_rel[row] = mean; g_rstd_rel[row] = r; }
        else            { g_mean_ent[row] = mean; g_rstd_ent[row] = r; }
    }
}

// ---------------- transpose params ----------------
__global__ void k_transpose4(const float* __restrict__ ea, const float* __restrict__ eb,
                             const float* __restrict__ ra, const float* __restrict__ rb) {
    int which = blockIdx.y;
    const float* in = (which == 0) ? ea : (which == 1) ? eb : (which == 2) ? ra : rb;
    float* out = (which == 0) ? g_alT : (which == 1) ? g_beT : (which == 2) ? g_ralT : g_rbeT;
    int idx = blockIdx.x * 256 + threadIdx.x;
    if (idx < Mv * 768) {
        int j = idx / 768;
        int e = idx - j * 768;
        out[idx] = in[e * Mv + j];
    }
}

// ---------------- split weights into bf16 hi/lo ----------------
__global__ void k_splitw(const float* __restrict__ egWb, const float* __restrict__ egWg,
                         const float* __restrict__ rgWb, const float* __restrict__ rgWg) {
    int idx = blockIdx.x * 256 + threadIdx.x;
    if (idx >= 1536 * 768) return;
    int which = blockIdx.y;
    int row = idx / 768, col = idx - row * 768;
    const float* Wb = which ? rgWb : egWb;
    const float* Wg = which ? rgWg : egWg;
    float x = (row < 768) ? Wb[row * 768 + col] : Wg[(row - 768) * 768 + col];
    __nv_bfloat16 hi = __float2bfloat16(x);
    __nv_bfloat16 lo = __float2bfloat16(x - __bfloat162float(hi));
    if (which) { g_W2hi[idx] = hi; g_W2lo[idx] = lo; }
    else       { g_W1hi[idx] = hi; g_W1lo[idx] = lo; }
}

// ---------------- erow / ecol ----------------
__global__ void k_rowcol_ent(const float* __restrict__ eh, const int* __restrict__ mir) {
    int b = blockIdx.x >> 7, i = blockIdx.x & 127;
    __shared__ int mids[Mv];
    if (threadIdx.x < Mv) mids[threadIdx.x] = mir[i * Mv + threadIdx.x];
    __syncthreads();
    for (int e = threadIdx.x; e < Ev; e += 256) {
        float aR = 0.f, aC = 0.f;
        #pragma unroll 4
        for (int j = 0; j < Mv; ++j) {
            float v = eh[((size_t)b * Sv + mids[j]) * Ev + e];
            aR = fmaf(v, g_alT[j * Ev + e], aR);
            aC = fmaf(v, g_beT[j * Ev + e], aC);
        }
        g_erow[(b * Ev + e) * Mv + i] = aR;
        g_ecol[(b * Ev + e) * Mv + i] = aC;
    }
}

// ---------------- rrow / rcol from rel_guided ----------------
__global__ void k_rowcol_rel(const float* __restrict__ rg) {
    int b = blockIdx.x >> 7, k = blockIdx.x & 127;
    const float* rgb = rg + (size_t)b * Mv * Mv * Rv;
    for (int r = threadIdx.x; r < Rv; r += 256) {
        float aR = 0.f, aC = 0.f;
        const float* prow = rgb + (size_t)k * Mv * Rv + r;
        const float* pcol = rgb + (size_t)k * Rv + r;
        #pragma unroll 4
        for (int j = 0; j < Mv; ++j) {
            aR = fmaf(prow[(size_t)j * Rv], g_ralT[j * Rv + r], aR);
            aC = fmaf(pcol[(size_t)j * Mv * Rv], g_rbeT[j * Rv + r], aC);
        }
        g_rrow[(b * Rv + r) * Mv + k] = aR;
        g_rcol[(b * Rv + r) * Mv + k] = aC;
    }
}

// ---------------- cond[(b,s)][r] -> bf16 hi/lo ----------------
__global__ void k_cond2(const float* __restrict__ lam, const int* __restrict__ upper) {
    int b = blockIdx.y;
    int s0 = blockIdx.x * 128;
    __shared__ float rrS[32][128], rcS[32][128], lamS[32];
    __shared__ int iS[128], jS[128];
    int tid = threadIdx.x;
    if (tid < 128) {
        int s = s0 + tid;
        if (s < Sv) { int u = upper[s]; iS[tid] = u >> 7; jS[tid] = u & 127; }
        else        { iS[tid] = 0; jS[tid] = 0; }
    }
    int s_loc = tid >> 1, rh = (tid & 1) * 16;
    int s = s0 + s_loc;
    for (int rch = 0; rch < 24; ++rch) {
        int r0 = rch * 32;
        __syncthreads();
        #pragma unroll
        for (int q = 0; q < 16; ++q) {
            int idx = q * 256 + tid;
            int rk = idx >> 7, mm = idx & 127;
            rrS[rk][mm] = g_rrow[((size_t)b * Rv + r0 + rk) * Mv + mm];
            rcS[rk][mm] = g_rcol[((size_t)b * Rv + r0 + rk) * Mv + mm];
        }
        if (tid < 32) lamS[tid] = lam[r0 + tid];
        __syncthreads();
        if (s < Sv) {
            int ii = iS[s_loc], jj = jS[s_loc];
            uint32_t hi8[8], lo8[8];
            #pragma unroll
            for (int p = 0; p < 8; ++p) {
                int r = rh + p * 2;
                float l0 = lamS[r], l1 = lamS[r + 1];
                float x0 = l0 * rrS[r][ii] * rcS[r][jj] + (1.f - l0) * rrS[r][jj] * rcS[r][ii];
                float x1 = l1 * rrS[r + 1][ii] * rcS[r + 1][jj] + (1.f - l1) * rrS[r + 1][jj] * rcS[r + 1][ii];
                __nv_bfloat162 h = __float22bfloat162_rn(make_float2(x0, x1));
                float2 hf = __bfloat1622float2(h);
                __nv_bfloat162 lo = __float22bfloat162_rn(make_float2(x0 - hf.x, x1 - hf.y));
                hi8[p] = *(uint32_t*)&h; lo8[p] = *(uint32_t*)&lo;
            }
            size_t off = ((size_t)b * Sv + s) * Rv + r0 + rh;
            *(uint4*)(g_cDhi + off)     = make_uint4(hi8[0], hi8[1], hi8[2], hi8[3]);
            *(uint4*)(g_cDhi + off + 8) = make_uint4(hi8[4], hi8[5], hi8[6], hi8[7]);
            *(uint4*)(g_cDlo + off)     = make_uint4(lo8[0], lo8[1], lo8[2], lo8[3]);
            *(uint4*)(g_cDlo + off + 8) = make_uint4(lo8[4], lo8[5], lo8[6], lo8[7]);
        }
    }
}

// ================= GEMM1: pipelined mma.sync bf16 3-pass -> rel_guided =================
// CTA: m=128 (j), n=256 (128 r x {Wb,Wg} interleaved), K=768 (e), chunks of 64, 2-stage.
__global__ __launch_bounds__(256, 1) void k_gemm1(
    const float* __restrict__ rel_hs, float* __restrict__ rel_out,
    const float* __restrict__ ebeta, const float* __restrict__ egam) {
    extern __shared__ char base[];
    const uint32_t sm0 = s2u(base);

    const int tid = threadIdx.x, w = tid >> 5, L = tid & 31;
    const int r0 = blockIdx.x * 128;
    const int byi = blockIdx.y;                // b*128 + i
    const int b = byi >> 7, i = byi & 127;
    const int m0w = (w >> 2) * 64, n0w = (w & 3) * 64;

    __shared__ float betS[128], gamS[128];
    if (tid < 128) { betS[tid] = ebeta[r0 + tid]; gamS[tid] = egam[r0 + tid]; }

    float acc[4][8][4];
    #pragma unroll
    for (int mt = 0; mt < 4; ++mt)
        #pragma unroll
        for (int nt = 0; nt < 8; ++nt)
            #pragma unroll
            for (int q = 0; q < 4; ++q) acc[mt][nt][q] = 0.f;

    const float* erow_bi = g_erow + (size_t)b * Ev * Mv + i;
    const float* ecol_b  = g_ecol + (size_t)b * Ev * Mv;

    const int jA = tid >> 1, khA = (tid & 1) * 32;
    const int bRow = tid >> 3, bSeg = tid & 7;        // B copy indices (8 iters of 256)
    const uint32_t aBase = sm0 + (uint32_t)(m0w + (L & 15)) * 144 + (uint32_t)(L >> 4) * 16;
    const uint32_t bBase = sm0 + B_HI + (uint32_t)(n0w + (L & 7)) * 144 + (uint32_t)((L >> 3) & 1) * 16;

    // ---- stage helpers ----
    auto stageB = [&](int ch, int st) {
        const int k0 = ch * 64;
        uint32_t sB = sm0 + st * STGSZ;
        #pragma unroll
        for (int q = 0; q < 8; ++q) {
            int row = bRow + q * 32;
            int src = r0 + (row >> 1) + (row & 1) * 768;
            size_t go = (size_t)src * 768 + k0 + bSeg * 8;
            uint32_t d = sB + (uint32_t)row * 144 + bSeg * 16;
            cpa16(d + B_HI, g_W1hi + go);
            cpa16(d + B_LO, g_W1lo + go);
        }
    };
    auto makeA = [&](int ch, int st) {
        const int k0 = ch * 64;
        char* sb = base + st * STGSZ;
        const float* pe = ecol_b + (size_t)(k0 + khA) * Mv + jA;
        const float* pr = erow_bi + (size_t)(k0 + khA) * Mv;
        char* Ah = sb + (size_t)jA * 144 + khA * 2;
        char* Al = Ah + A_LO;
        #pragma unroll
        for (int g = 0; g < 4; ++g) {
            uint32_t hi[4], lo[4];
            #pragma unroll
            for (int p = 0; p < 4; ++p) {
                int kk = g * 8 + p * 2;
                float x0 = pe[(size_t)kk * Mv] * pr[(size_t)kk * Mv];
                float x1 = pe[(size_t)(kk + 1) * Mv] * pr[(size_t)(kk + 1) * Mv];
                __nv_bfloat162 h = __float22bfloat162_rn(make_float2(x0, x1));
                float2 hf = __bfloat1622float2(h);
                __nv_bfloat162 l = __float22bfloat162_rn(make_float2(x0 - hf.x, x1 - hf.y));
                hi[p] = *(uint32_t*)&h; lo[p] = *(uint32_t*)&l;
            }
            *(uint4*)(Ah + g * 16) = make_uint4(hi[0], hi[1], hi[2], hi[3]);
            *(uint4*)(Al + g * 16) = make_uint4(lo[0], lo[1], lo[2], lo[3]);
        }
    };

    // prologue
    stageB(0, 0);
    CP_COMMIT();
    makeA(0, 0);

    for (int ch = 0; ch < 12; ++ch) {
        const int cur = ch & 1, nxt = cur ^ 1;
        CP_WAIT0();
        __syncthreads();
        if (ch < 11) {
            stageB(ch + 1, nxt);
            CP_COMMIT();
            makeA(ch + 1, nxt);
        }
        const uint32_t aA = aBase + cur * STGSZ;
        const uint32_t bA = bBase + cur * STGSZ;
        #pragma unroll
        for (int ks = 0; ks < 64; ks += 16) {
            uint32_t ah[4][4], al[4][4];
            #pragma unroll
            for (int mt = 0; mt < 4; ++mt) {
                ldsm_x4(ah[mt], aA + mt * 2304 + ks * 2);
                ldsm_x4(al[mt], aA + A_LO + mt * 2304 + ks * 2);
            }
            #pragma unroll
            for (int nt = 0; nt < 8; ++nt) {
                uint32_t bh[2], bl[2];
                ldsm_x2(bh, bA + nt * 1152 + ks * 2);
                ldsm_x2(bl, bA + (B_LO - B_HI) + nt * 1152 + ks * 2);
                #pragma unroll
                for (int mt = 0; mt < 4; ++mt) {
                    mma16816(acc[mt][nt], ah[mt], bh);
                    mma16816(acc[mt][nt], ah[mt], bl);
                    mma16816(acc[mt][nt], al[mt], bh);
                }
            }
        }
    }

    // epilogue
    const int gid = L >> 2, tig = L & 3;
    #pragma unroll
    for (int mt = 0; mt < 4; ++mt) {
        int j1 = m0w + mt * 16 + gid;
        int row1 = byi * 128 + j1, row2 = row1 + 8;
        float mn1 = g_mean_rel[row1], rs1 = g_rstd_rel[row1];
        float mn2 = g_mean_rel[row2], rs2 = g_rstd_rel[row2];
        const float* x1 = rel_hs + (size_t)row1 * 768;
        const float* x2 = rel_hs + (size_t)row2 * 768;
        float* o1 = rel_out + (size_t)row1 * 768;
        float* o2 = rel_out + (size_t)row2 * 768;
        #pragma unroll
        for (int nt = 0; nt < 8; ++nt) {
            int rl = (n0w >> 1) + nt * 4 + tig;
            int r = r0 + rl;
            const float* c = acc[mt][nt];
            o1[r] = (x1[r] - mn1) * rs1 * (c[1] + gamS[rl]) + c[0] + betS[rl];
            o2[r] = (x2[r] - mn2) * rs2 * (c[3] + gamS[rl]) + c[2] + betS[rl];
        }
    }
}

// ================= GEMM2: pipelined (pure cp.async operands) -> ent_guided =================
// CTA: m=128 ((b,s) rows), n=256 (128 e x {Wb,Wg} interleaved), K=768 (r), 2-stage.
__global__ __launch_bounds__(256, 1) void k_gemm2(
    const float* __restrict__ ent_hs, float* __restrict__ ent_out,
    const float* __restrict__ rbeta, const float* __restrict__ rgam) {
    extern __shared__ char base[];
    const uint32_t sm0 = s2u(base);

    const int tid = threadIdx.x, w = tid >> 5, L = tid & 31;
    const int e0 = blockIdx.x * 128;
    const int m0 = blockIdx.y * 128;
    const int m0w = (w >> 2) * 64, n0w = (w & 3) * 64;

    __shared__ float betS[128], gamS[128];
    if (tid < 128) { betS[tid] = rbeta[e0 + tid]; gamS[tid] = rgam[e0 + tid]; }

    float acc[4][8][4];
    #pragma unroll
    for (int mt = 0; mt < 4; ++mt)
        #pragma unroll
        for (int nt = 0; nt < 8; ++nt)
            #pragma unroll
            for (int q = 0; q < 4; ++q) acc[mt][nt][q] = 0.f;

    const int cRow = tid >> 3, cSeg = tid & 7;
    const uint32_t aBase = sm0 + (uint32_t)(m0w + (L & 15)) * 144 + (uint32_t)(L >> 4) * 16;
    const uint32_t bBase = sm0 + B_HI + (uint32_t)(n0w + (L & 7)) * 144 + (uint32_t)((L >> 3) & 1) * 16;

    auto stage = [&](int ch, int st) {
        const int k0 = ch * 64;
        uint32_t sB = sm0 + st * STGSZ;
        // A: 128 rows from g_cDhi/lo
        #pragma unroll
        for (int q = 0; q < 4; ++q) {
            int row = cRow + q * 32;
            size_t go = (size_t)(m0 + row) * Rv + k0 + cSeg * 8;
            uint32_t d = sB + (uint32_t)row * 144 + cSeg * 16;
            cpa16(d, g_cDhi + go);
            cpa16(d + A_LO, g_cDlo + go);
        }
        // B: 256 interleaved weight rows
        #pragma unroll
        for (int q = 0; q < 8; ++q) {
            int row = cRow + q * 32;
            int src = e0 + (row >> 1) + (row & 1) * 768;
            size_t go = (size_t)src * 768 + k0 + cSeg * 8;
            uint32_t d = sB + (uint32_t)row * 144 + cSeg * 16;
            cpa16(d + B_HI, g_W2hi + go);
            cpa16(d + B_LO, g_W2lo + go);
        }
    };

    stage(0, 0);
    CP_COMMIT();

    for (int ch = 0; ch < 12; ++ch) {
        const int cur = ch & 1, nxt = cur ^ 1;
        CP_WAIT0();
        __syncthreads();
        if (ch < 11) {
            stage(ch + 1, nxt);
            CP_COMMIT();
        }
        const uint32_t aA = aBase + cur * STGSZ;
        const uint32_t bA = bBase + cur * STGSZ;
        #pragma unroll
        for (int ks = 0; ks < 64; ks += 16) {
            uint32_t ah[4][4], al[4][4];
            #pragma unroll
            for (int mt = 0; mt < 4; ++mt) {
                ldsm_x4(ah[mt], aA + mt * 2304 + ks * 2);
                ldsm_x4(al[mt], aA + A_LO + mt * 2304 + ks * 2);
            }
            #pragma unroll
            for (int nt = 0; nt < 8; ++nt) {
                uint32_t bh[2], bl[2];
                ldsm_x2(bh, bA + nt * 1152 + ks * 2);
                ldsm_x2(bl, bA + (B_LO - B_HI) + nt * 1152 + ks * 2);
                #pragma unroll
                for (int mt = 0; mt < 4; ++mt) {
                    mma16816(acc[mt][nt], ah[mt], bh);
                    mma16816(acc[mt][nt], ah[mt], bl);
                    mma16816(acc[mt][nt], al[mt], bh);
                }
            }
        }
    }

    const int gid = L >> 2, tig = L & 3;
    #pragma unroll
    for (int mt = 0; mt < 4; ++mt) {
        int row1 = m0 + m0w + mt * 16 + gid, row2 = row1 + 8;
        float mn1 = g_mean_ent[row1], rs1 = g_rstd_ent[row1];
        float mn2 = g_mean_ent[row2], rs2 = g_rstd_ent[row2];
        const float* x1 = ent_hs + (size_t)row1 * 768;
        const float* x2 = ent_hs + (size_t)row2 * 768;
        float* o1 = ent_out + (size_t)row1 * 768;
        float* o2 = ent_out + (size_t)row2 * 768;
        #pragma unroll
        for (int nt = 0; nt < 8; ++nt) {
            int el = (n0w >> 1) + nt * 4 + tig;
            int e = e0 + el;
            const float* c = acc[mt][nt];
            o1[e] = (x1[e] - mn1) * rs1 * (c[1] + gamS[el]) + c[0] + betS[el];
            o2[e] = (x2[e] - mn2) * rs2 * (c[3] + gamS[el]) + c[2] + betS[el];
        }
    }
}

// ---------------- launch ----------------
extern "C" void kernel_launch(void* const* d_in, const int* in_sizes, int n_in,
                              void* d_out, int out_size) {
    const float* ent_hs    = (const float*)d_in[0];
    const float* rel_hs    = (const float*)d_in[1];
    const float* ent_alpha = (const float*)d_in[2];
    const float* ent_beta  = (const float*)d_in[3];
    const float* rel_alpha = (const float*)d_in[4];
    const float* rel_beta  = (const float*)d_in[5];
    const float* lam       = (const float*)d_in[6];
    const float* egr_Wb    = (const float*)d_in[7];
    const float* egr_Wg    = (const float*)d_in[8];
    const float* egr_beta  = (const float*)d_in[9];
    const float* egr_gamma = (const float*)d_in[10];
    const float* rge_Wb    = (const float*)d_in[11];
    const float* rge_Wg    = (const float*)d_in[12];
    const float* rge_beta  = (const float*)d_in[13];
    const float* rge_gamma = (const float*)d_in[14];
    const int*   mirror    = (const int*)d_in[15];
    const int*   upper     = (const int*)d_in[16];

    float* ent_out = (float*)d_out;                              // [B,S,E]
    float* rel_out = (float*)d_out + (size_t)Bc * Sv * Ev;       // [B,M,M,R]

    cudaFuncSetAttribute(k_gemm1, cudaFuncAttributeMaxDynamicSharedMemorySize, DSMEM);
    cudaFuncSetAttribute(k_gemm2, cudaFuncAttributeMaxDynamicSharedMemorySize, DSMEM);

    k_meanvar<<<Bc * Mv * Mv, 256>>>(rel_hs, 0);
    k_meanvar<<<BSv, 256>>>(ent_hs, 1);
    k_transpose4<<<dim3((Mv * 768 + 255) / 256, 4), 256>>>(ent_alpha, ent_beta, rel_alpha, rel_beta);
    k_splitw<<<dim3((1536 * 768 + 255) / 256, 2), 256>>>(egr_Wb, egr_Wg, rge_Wb, rge_Wg);
    k_rowcol_ent<<<Bc * Mv, 256>>>(ent_hs, mirror);
    k_gemm1<<<dim3(6, Bc * Mv), 256, DSMEM>>>(rel_hs, rel_out, egr_beta, egr_gamma);
    k_rowcol_rel<<<Bc * Mv, 256>>>(rel_out);
    k_cond2<<<dim3((Sv + 127) / 128, Bc), 256>>>(lam, upper);
    k_gemm2<<<dim3(6, BSv / 128), 256, DSMEM>>>(ent_hs, ent_out, rge_beta, rge_gamma);
}

// round 7
// speedup vs baseline: 2.2652x; 1.0018x over previous
#include <cuda_runtime.h>
#include <cuda_bf16.h>
#include <cstdint>

constexpr int Bc = 4;
constexpr int Mv = 128;
constexpr int Ev = 768;
constexpr int Rv = 768;
constexpr int Sv = Mv * (Mv + 1) / 2;   // 8256
constexpr int BSv = Bc * Sv;            // 33024

// ---------------- device scratch ----------------
__device__ float g_erow[Bc * Ev * Mv];     // [b][e][i]
__device__ float g_ecol[Bc * Ev * Mv];     // [b][e][j]
__device__ float g_rrow[Bc * Rv * Mv];
__device__ float g_rcol[Bc * Rv * Mv];
__device__ float g_mean_rel[Bc * Mv * Mv];
__device__ float g_rstd_rel[Bc * Mv * Mv];
__device__ float g_mean_ent[BSv];
__device__ float g_rstd_ent[BSv];
__device__ float g_alT[Mv * Ev];
__device__ float g_beT[Mv * Ev];
__device__ float g_ralT[Mv * Rv];
__device__ float g_rbeT[Mv * Rv];
__device__ __nv_bfloat16 g_cDhi[(size_t)BSv * Rv];
__device__ __nv_bfloat16 g_cDlo[(size_t)BSv * Rv];
__device__ __nv_bfloat16 g_W1hi[1536 * 768];           // rows 0..767 egr_Wb, 768..1535 egr_Wg
__device__ __nv_bfloat16 g_W1lo[1536 * 768];
__device__ __nv_bfloat16 g_W2hi[1536 * 768];           // rows 0..767 rge_Wb, 768..1535 rge_Wg
__device__ __nv_bfloat16 g_W2lo[1536 * 768];

// ---------------- PTX helpers (baseline-target only) ----------------
__device__ __forceinline__ uint32_t s2u(const void* p) {
    uint32_t a;
    asm("{ .reg .u64 t; cvta.to.shared.u64 t, %1; cvt.u32.u64 %0, t; }" : "=r"(a) : "l"(p));
    return a;
}
__device__ __forceinline__ void ldsm_x4(uint32_t r[4], uint32_t a) {
    asm volatile("ldmatrix.sync.aligned.m8n8.x4.shared.b16 {%0,%1,%2,%3}, [%4];"
        : "=r"(r[0]), "=r"(r[1]), "=r"(r[2]), "=r"(r[3]) : "r"(a));
}
__device__ __forceinline__ void mma16816(float c[4], const uint32_t a[4], const uint32_t b[2]) {
    asm volatile("mma.sync.aligned.m16n8k16.row.col.f32.bf16.bf16.f32 "
        "{%0,%1,%2,%3}, {%4,%5,%6,%7}, {%8,%9}, {%0,%1,%2,%3};"
        : "+f"(c[0]), "+f"(c[1]), "+f"(c[2]), "+f"(c[3])
        : "r"(a[0]), "r"(a[1]), "r"(a[2]), "r"(a[3]), "r"(b[0]), "r"(b[1]));
}
__device__ __forceinline__ void cpa16(uint32_t dst, const void* src) {
    asm volatile("cp.async.cg.shared.global [%0], [%1], 16;" :: "r"(dst), "l"(src));
}
#define CP_COMMIT() asm volatile("cp.async.commit_group;" ::: "memory")
#define CP_WAIT0()  asm volatile("cp.async.wait_group 0;" ::: "memory")

// smem stage layout (bytes), padded stride 72 bf16 = 144B (conflict-free ldmatrix)
constexpr int A_LO = 18432;            // 128*144
constexpr int B_HI = 36864;
constexpr int B_LO = 73728;
constexpr int STGSZ = 110592;
constexpr int DSMEM = 2 * STGSZ;       // 221184 B

// ---------------- mean / rstd (float4 loads) ----------------
__global__ void k_meanvar(const float* __restrict__ x, int which) {
    int row = blockIdx.x;
    const float4* p = (const float4*)(x + (size_t)row * 768);
    float s = 0.f, ss = 0.f;
    for (int t = threadIdx.x; t < 192; t += 256) {
        float4 v = p[t];
        s += v.x + v.y + v.z + v.w;
        ss = fmaf(v.x, v.x, ss); ss = fmaf(v.y, v.y, ss);
        ss = fmaf(v.z, v.z, ss); ss = fmaf(v.w, v.w, ss);
    }
    #pragma unroll
    for (int o = 16; o; o >>= 1) {
        s  += __shfl_xor_sync(0xffffffffu, s, o);
        ss += __shfl_xor_sync(0xffffffffu, ss, o);
    }
    __shared__ float sm[8], sm2[8];
    int w = threadIdx.x >> 5;
    if ((threadIdx.x & 31) == 0) { sm[w] = s; sm2[w] = ss; }
    __syncthreads();
    if (threadIdx.x == 0) {
        float S = 0.f, SS = 0.f;
        #pragma unroll
        for (int q = 0; q < 8; ++q) { S += sm[q]; SS += sm2[q]; }
        float mean = S * (1.f / 768.f);
        float var  = SS * (1.f / 768.f) - mean * mean;
        float d    = var + 1e-12f;
        float r    = 1.f / (d * d);            // faithful: std = (var+eps)^2
        if (which == 0) { g_mean_rel[row] = mean; g_rstd_rel[row] = r; }
        else            { g_mean_ent[row] = mean; g_rstd_ent[row] = r; }
    }
}

// ---------------- transpose params ----------------
__global__ void k_transpose4(const float* __restrict__ ea, const float* __restrict__ eb,
                             const float* __restrict__ ra, const float* __restrict__ rb) {
    int which = blockIdx.y;
    const float* in = (which == 0) ? ea : (which == 1) ? eb : (which == 2) ? ra : rb;
    float* out = (which == 0) ? g_alT : (which == 1) ? g_beT : (which == 2) ? g_ralT : g_rbeT;
    int idx = blockIdx.x * 256 + threadIdx.x;
    if (idx < Mv * 768) {
        int j = idx / 768;
        int e = idx - j * 768;
        out[idx] = in[e * Mv + j];
    }
}

// ---------------- split weights into bf16 hi/lo ----------------
__global__ void k_splitw(const float* __restrict__ egWb, const float* __restrict__ egWg,
                         const float* __restrict__ rgWb, const float* __restrict__ rgWg) {
    int idx = blockIdx.x * 256 + threadIdx.x;
    if (idx >= 1536 * 768) return;
    int which = blockIdx.y;
    int row = idx / 768, col = idx - row * 768;
    const float* Wb = which ? rgWb : egWb;
    const float* Wg = which ? rgWg : egWg;
    float x = (row < 768) ? Wb[row * 768 + col] : Wg[(row - 768) * 768 + col];
    __nv_bfloat16 hi = __float2bfloat16(x);
    __nv_bfloat16 lo = __float2bfloat16(x - __bfloat162float(hi));
    if (which) { g_W2hi[idx] = hi; g_W2lo[idx] = lo; }
    else       { g_W1hi[idx] = hi; g_W1lo[idx] = lo; }
}

// ---------------- erow / ecol ----------------
__global__ void k_rowcol_ent(const float* __restrict__ eh, const int* __restrict__ mir) {
    int b = blockIdx.x >> 7, i = blockIdx.x & 127;
    __shared__ int mids[Mv];
    if (threadIdx.x < Mv) mids[threadIdx.x] = mir[i * Mv + threadIdx.x];
    __syncthreads();
    for (int e = threadIdx.x; e < Ev; e += 256) {
        float aR = 0.f, aC = 0.f;
        #pragma unroll 4
        for (int j = 0; j < Mv; ++j) {
            float v = eh[((size_t)b * Sv + mids[j]) * Ev + e];
            aR = fmaf(v, g_alT[j * Ev + e], aR);
            aC = fmaf(v, g_beT[j * Ev + e], aC);
        }
        g_erow[(b * Ev + e) * Mv + i] = aR;
        g_ecol[(b * Ev + e) * Mv + i] = aC;
    }
}

// ---------------- rrow / rcol from rel_guided ----------------
__global__ void k_rowcol_rel(const float* __restrict__ rg) {
    int b = blockIdx.x >> 7, k = blockIdx.x & 127;
    const float* rgb = rg + (size_t)b * Mv * Mv * Rv;
    for (int r = threadIdx.x; r < Rv; r += 256) {
        float aR = 0.f, aC = 0.f;
        const float* prow = rgb + (size_t)k * Mv * Rv + r;
        const float* pcol = rgb + (size_t)k * Rv + r;
        #pragma unroll 4
        for (int j = 0; j < Mv; ++j) {
            aR = fmaf(prow[(size_t)j * Rv], g_ralT[j * Rv + r], aR);
            aC = fmaf(pcol[(size_t)j * Mv * Rv], g_rbeT[j * Rv + r], aC);
        }
        g_rrow[(b * Rv + r) * Mv + k] = aR;
        g_rcol[(b * Rv + r) * Mv + k] = aC;
    }
}

// ---------------- cond[(b,s)][r] -> bf16 hi/lo ----------------
__global__ void k_cond2(const float* __restrict__ lam, const int* __restrict__ upper) {
    int b = blockIdx.y;
    int s0 = blockIdx.x * 128;
    __shared__ float rrS[32][128], rcS[32][128], lamS[32];
    __shared__ int iS[128], jS[128];
    int tid = threadIdx.x;
    if (tid < 128) {
        int s = s0 + tid;
        if (s < Sv) { int u = upper[s]; iS[tid] = u >> 7; jS[tid] = u & 127; }
        else        { iS[tid] = 0; jS[tid] = 0; }
    }
    int s_loc = tid >> 1, rh = (tid & 1) * 16;
    int s = s0 + s_loc;
    for (int rch = 0; rch < 24; ++rch) {
        int r0 = rch * 32;
        __syncthreads();
        #pragma unroll
        for (int q = 0; q < 16; ++q) {
            int idx = q * 256 + tid;
            int rk = idx >> 7, mm = idx & 127;
            rrS[rk][mm] = g_rrow[((size_t)b * Rv + r0 + rk) * Mv + mm];
            rcS[rk][mm] = g_rcol[((size_t)b * Rv + r0 + rk) * Mv + mm];
        }
        if (tid < 32) lamS[tid] = lam[r0 + tid];
        __syncthreads();
        if (s < Sv) {
            int ii = iS[s_loc], jj = jS[s_loc];
            uint32_t hi8[8], lo8[8];
            #pragma unroll
            for (int p = 0; p < 8; ++p) {
                int r = rh + p * 2;
                float l0 = lamS[r], l1 = lamS[r + 1];
                float x0 = l0 * rrS[r][ii] * rcS[r][jj] + (1.f - l0) * rrS[r][jj] * rcS[r][ii];
                float x1 = l1 * rrS[r + 1][ii] * rcS[r + 1][jj] + (1.f - l1) * rrS[r + 1][jj] * rcS[r + 1][ii];
                __nv_bfloat162 h = __float22bfloat162_rn(make_float2(x0, x1));
                float2 hf = __bfloat1622float2(h);
                __nv_bfloat162 lo = __float22bfloat162_rn(make_float2(x0 - hf.x, x1 - hf.y));
                hi8[p] = *(uint32_t*)&h; lo8[p] = *(uint32_t*)&lo;
            }
            size_t off = ((size_t)b * Sv + s) * Rv + r0 + rh;
            *(uint4*)(g_cDhi + off)     = make_uint4(hi8[0], hi8[1], hi8[2], hi8[3]);
            *(uint4*)(g_cDhi + off + 8) = make_uint4(hi8[4], hi8[5], hi8[6], hi8[7]);
            *(uint4*)(g_cDlo + off)     = make_uint4(lo8[0], lo8[1], lo8[2], lo8[3]);
            *(uint4*)(g_cDlo + off + 8) = make_uint4(lo8[4], lo8[5], lo8[6], lo8[7]);
        }
    }
}

// ================= GEMM1: 512-thread pipelined mma.sync 3-pass -> rel_guided =================
// CTA m=128 (j) x n=256 (128 r x {Wb,Wg}); 16 warps, warp tile 32x64; K chunks of 64, 2-stage.
__global__ __launch_bounds__(512, 1) void k_gemm1(
    const float* __restrict__ rel_hs, float* __restrict__ rel_out,
    const float* __restrict__ ebeta, const float* __restrict__ egam) {
    extern __shared__ char base[];
    const uint32_t sm0 = s2u(base);

    const int tid = threadIdx.x, w = tid >> 5, L = tid & 31;
    const int r0 = blockIdx.x * 128;
    const int byi = blockIdx.y;                // b*128 + i
    const int b = byi >> 7, i = byi & 127;
    const int m0w = (w >> 2) * 32, n0w = (w & 3) * 64;

    __shared__ float betS[128], gamS[128];
    if (tid < 128) { betS[tid] = ebeta[r0 + tid]; gamS[tid] = egam[r0 + tid]; }

    float acc[2][8][4];
    #pragma unroll
    for (int mt = 0; mt < 2; ++mt)
        #pragma unroll
        for (int nt = 0; nt < 8; ++nt)
            #pragma unroll
            for (int q = 0; q < 4; ++q) acc[mt][nt][q] = 0.f;

    const float* erow_bi = g_erow + (size_t)b * Ev * Mv + i;
    const float* ecol_b  = g_ecol + (size_t)b * Ev * Mv;

    // A construct: 512 threads, each covers 16 k of one row
    const int jA = tid >> 2, khA = (tid & 3) * 16;
    // B cp.async: 512 threads
    const int bRow = tid >> 3, bSeg = tid & 7;
    // ldmatrix addresses
    const uint32_t aBase = sm0 + (uint32_t)(m0w + (L & 15)) * 144 + (uint32_t)(L >> 4) * 16;
    const uint32_t bBase = sm0 + B_HI
        + (uint32_t)(n0w + (L & 7) + ((L >> 4) << 3)) * 144 + (uint32_t)((L >> 3) & 1) * 16;

    auto stageB = [&](int ch, int st) {
        const int k0 = ch * 64;
        uint32_t sB = sm0 + st * STGSZ;
        #pragma unroll
        for (int q = 0; q < 4; ++q) {
            int row = bRow + q * 64;
            int src = r0 + (row >> 1) + (row & 1) * 768;
            size_t go = (size_t)src * 768 + k0 + bSeg * 8;
            uint32_t d = sB + (uint32_t)row * 144 + bSeg * 16;
            cpa16(d + B_HI, g_W1hi + go);
            cpa16(d + B_LO, g_W1lo + go);
        }
    };
    auto makeA = [&](int ch, int st) {
        const int k0 = ch * 64;
        char* sb = base + st * STGSZ;
        const float* pe = ecol_b + (size_t)(k0 + khA) * Mv + jA;
        const float* pr = erow_bi + (size_t)(k0 + khA) * Mv;
        char* Ah = sb + (size_t)jA * 144 + khA * 2;
        char* Al = Ah + A_LO;
        #pragma unroll
        for (int g = 0; g < 2; ++g) {
            uint32_t hi[4], lo[4];
            #pragma unroll
            for (int p = 0; p < 4; ++p) {
                int kk = g * 8 + p * 2;
                float x0 = pe[(size_t)kk * Mv] * pr[(size_t)kk * Mv];
                float x1 = pe[(size_t)(kk + 1) * Mv] * pr[(size_t)(kk + 1) * Mv];
                __nv_bfloat162 h = __float22bfloat162_rn(make_float2(x0, x1));
                float2 hf = __bfloat1622float2(h);
                __nv_bfloat162 l = __float22bfloat162_rn(make_float2(x0 - hf.x, x1 - hf.y));
                hi[p] = *(uint32_t*)&h; lo[p] = *(uint32_t*)&l;
            }
            *(uint4*)(Ah + g * 16) = make_uint4(hi[0], hi[1], hi[2], hi[3]);
            *(uint4*)(Al + g * 16) = make_uint4(lo[0], lo[1], lo[2], lo[3]);
        }
    };

    stageB(0, 0);
    CP_COMMIT();
    makeA(0, 0);

    for (int ch = 0; ch < 12; ++ch) {
        const int cur = ch & 1, nxt = cur ^ 1;
        CP_WAIT0();
        __syncthreads();
        if (ch < 11) {
            stageB(ch + 1, nxt);
            CP_COMMIT();
            makeA(ch + 1, nxt);
        }
        const uint32_t aA = aBase + cur * STGSZ;
        const uint32_t bA = bBase + cur * STGSZ;
        #pragma unroll
        for (int ks = 0; ks < 64; ks += 16) {
            uint32_t ah[2][4], al[2][4];
            #pragma unroll
            for (int mt = 0; mt < 2; ++mt) {
                ldsm_x4(ah[mt], aA + mt * 2304 + ks * 2);
                ldsm_x4(al[mt], aA + A_LO + mt * 2304 + ks * 2);
            }
            #pragma unroll
            for (int np = 0; np < 4; ++np) {
                uint32_t bh[4], bl[4];
                ldsm_x4(bh, bA + np * 2304 + ks * 2);
                ldsm_x4(bl, bA + (B_LO - B_HI) + np * 2304 + ks * 2);
                #pragma unroll
                for (int mt = 0; mt < 2; ++mt) {
                    mma16816(acc[mt][2 * np],     ah[mt], bh);
                    mma16816(acc[mt][2 * np],     ah[mt], bl);
                    mma16816(acc[mt][2 * np],     al[mt], bh);
                    mma16816(acc[mt][2 * np + 1], ah[mt], bh + 2);
                    mma16816(acc[mt][2 * np + 1], ah[mt], bl + 2);
                    mma16816(acc[mt][2 * np + 1], al[mt], bh + 2);
                }
            }
        }
    }

    // epilogue
    const int gid = L >> 2, tig = L & 3;
    #pragma unroll
    for (int mt = 0; mt < 2; ++mt) {
        int j1 = m0w + mt * 16 + gid;
        int row1 = byi * 128 + j1, row2 = row1 + 8;
        float mn1 = g_mean_rel[row1], rs1 = g_rstd_rel[row1];
        float mn2 = g_mean_rel[row2], rs2 = g_rstd_rel[row2];
        const float* x1 = rel_hs + (size_t)row1 * 768;
        const float* x2 = rel_hs + (size_t)row2 * 768;
        float* o1 = rel_out + (size_t)row1 * 768;
        float* o2 = rel_out + (size_t)row2 * 768;
        #pragma unroll
        for (int nt = 0; nt < 8; ++nt) {
            int rl = (n0w >> 1) + nt * 4 + tig;
            int r = r0 + rl;
            const float* c = acc[mt][nt];
            o1[r] = (x1[r] - mn1) * rs1 * (c[1] + gamS[rl]) + c[0] + betS[rl];
            o2[r] = (x2[r] - mn2) * rs2 * (c[3] + gamS[rl]) + c[2] + betS[rl];
        }
    }
}

// ================= GEMM2: 512-thread pipelined (pure cp.async) -> ent_guided =================
__global__ __launch_bounds__(512, 1) void k_gemm2(
    const float* __restrict__ ent_hs, float* __restrict__ ent_out,
    const float* __restrict__ rbeta, const float* __restrict__ rgam) {
    extern __shared__ char base[];
    const uint32_t sm0 = s2u(base);

    const int tid = threadIdx.x, w = tid >> 5, L = tid & 31;
    const int e0 = blockIdx.x * 128;
    const int m0 = blockIdx.y * 128;
    const int m0w = (w >> 2) * 32, n0w = (w & 3) * 64;

    __shared__ float betS[128], gamS[128];
    if (tid < 128) { betS[tid] = rbeta[e0 + tid]; gamS[tid] = rgam[e0 + tid]; }

    float acc[2][8][4];
    #pragma unroll
    for (int mt = 0; mt < 2; ++mt)
        #pragma unroll
        for (int nt = 0; nt < 8; ++nt)
            #pragma unroll
            for (int q = 0; q < 4; ++q) acc[mt][nt][q] = 0.f;

    const int cRow = tid >> 3, cSeg = tid & 7;
    const uint32_t aBase = sm0 + (uint32_t)(m0w + (L & 15)) * 144 + (uint32_t)(L >> 4) * 16;
    const uint32_t bBase = sm0 + B_HI
        + (uint32_t)(n0w + (L & 7) + ((L >> 4) << 3)) * 144 + (uint32_t)((L >> 3) & 1) * 16;

    auto stage = [&](int ch, int st) {
        const int k0 = ch * 64;
        uint32_t sB = sm0 + st * STGSZ;
        #pragma unroll
        for (int q = 0; q < 2; ++q) {
            int row = cRow + q * 64;
            size_t go = (size_t)(m0 + row) * Rv + k0 + cSeg * 8;
            uint32_t d = sB + (uint32_t)row * 144 + cSeg * 16;
            cpa16(d, g_cDhi + go);
            cpa16(d + A_LO, g_cDlo + go);
        }
        #pragma unroll
        for (int q = 0; q < 4; ++q) {
            int row = cRow + q * 64;
            int src = e0 + (row >> 1) + (row & 1) * 768;
            size_t go = (size_t)src * 768 + k0 + cSeg * 8;
            uint32_t d = sB + (uint32_t)row * 144 + cSeg * 16;
            cpa16(d + B_HI, g_W2hi + go);
            cpa16(d + B_LO, g_W2lo + go);
        }
    };

    stage(0, 0);
    CP_COMMIT();

    for (int ch = 0; ch < 12; ++ch) {
        const int cur = ch & 1, nxt = cur ^ 1;
        CP_WAIT0();
        __syncthreads();
        if (ch < 11) {
            stage(ch + 1, nxt);
            CP_COMMIT();
        }
        const uint32_t aA = aBase + cur * STGSZ;
        const uint32_t bA = bBase + cur * STGSZ;
        #pragma unroll
        for (int ks = 0; ks < 64; ks += 16) {
            uint32_t ah[2][4], al[2][4];
            #pragma unroll
            for (int mt = 0; mt < 2; ++mt) {
                ldsm_x4(ah[mt], aA + mt * 2304 + ks * 2);
                ldsm_x4(al[mt], aA + A_LO + mt * 2304 + ks * 2);
            }
            #pragma unroll
            for (int np = 0; np < 4; ++np) {
                uint32_t bh[4], bl[4];
                ldsm_x4(bh, bA + np * 2304 + ks * 2);
                ldsm_x4(bl, bA + (B_LO - B_HI) + np * 2304 + ks * 2);
                #pragma unroll
                for (int mt = 0; mt < 2; ++mt) {
                    mma16816(acc[mt][2 * np],     ah[mt], bh);
                    mma16816(acc[mt][2 * np],     ah[mt], bl);
                    mma16816(acc[mt][2 * np],     al[mt], bh);
                    mma16816(acc[mt][2 * np + 1], ah[mt], bh + 2);
                    mma16816(acc[mt][2 * np + 1], ah[mt], bl + 2);
                    mma16816(acc[mt][2 * np + 1], al[mt], bh + 2);
                }
            }
        }
    }

    const int gid = L >> 2, tig = L & 3;
    #pragma unroll
    for (int mt = 0; mt < 2; ++mt) {
        int row1 = m0 + m0w + mt * 16 + gid, row2 = row1 + 8;
        float mn1 = g_mean_ent[row1], rs1 = g_rstd_ent[row1];
        float mn2 = g_mean_ent[row2], rs2 = g_rstd_ent[row2];
        const float* x1 = ent_hs + (size_t)row1 * 768;
        const float* x2 = ent_hs + (size_t)row2 * 768;
        float* o1 = ent_out + (size_t)row1 * 768;
        float* o2 = ent_out + (size_t)row2 * 768;
        #pragma unroll
        for (int nt = 0; nt < 8; ++nt) {
            int el = (n0w >> 1) + nt * 4 + tig;
            int e = e0 + el;
            const float* c = acc[mt][nt];
            o1[e] = (x1[e] - mn1) * rs1 * (c[1] + gamS[el]) + c[0] + betS[el];
            o2[e] = (x2[e] - mn2) * rs2 * (c[3] + gamS[el]) + c[2] + betS[el];
        }
    }
}

// ---------------- launch ----------------
extern "C" void kernel_launch(void* const* d_in, const int* in_sizes, int n_in,
                              void* d_out, int out_size) {
    const float* ent_hs    = (const float*)d_in[0];
    const float* rel_hs    = (const float*)d_in[1];
    const float* ent_alpha = (const float*)d_in[2];
    const float* ent_beta  = (const float*)d_in[3];
    const float* rel_alpha = (const float*)d_in[4];
    const float* rel_beta  = (const float*)d_in[5];
    const float* lam       = (const float*)d_in[6];
    const float* egr_Wb    = (const float*)d_in[7];
    const float* egr_Wg    = (const float*)d_in[8];
    const float* egr_beta  = (const float*)d_in[9];
    const float* egr_gamma = (const float*)d_in[10];
    const float* rge_Wb    = (const float*)d_in[11];
    const float* rge_Wg    = (const float*)d_in[12];
    const float* rge_beta  = (const float*)d_in[13];
    const float* rge_gamma = (const float*)d_in[14];
    const int*   mirror    = (const int*)d_in[15];
    const int*   upper     = (const int*)d_in[16];

    float* ent_out = (float*)d_out;                              // [B,S,E]
    float* rel_out = (float*)d_out + (size_t)Bc * Sv * Ev;       // [B,M,M,R]

    cudaFuncSetAttribute(k_gemm1, cudaFuncAttributeMaxDynamicSharedMemorySize, DSMEM);
    cudaFuncSetAttribute(k_gemm2, cudaFuncAttributeMaxDynamicSharedMemorySize, DSMEM);

    k_meanvar<<<Bc * Mv * Mv, 256>>>(rel_hs, 0);
    k_meanvar<<<BSv, 256>>>(ent_hs, 1);
    k_transpose4<<<dim3((Mv * 768 + 255) / 256, 4), 256>>>(ent_alpha, ent_beta, rel_alpha, rel_beta);
    k_splitw<<<dim3((1536 * 768 + 255) / 256, 2), 256>>>(egr_Wb, egr_Wg, rge_Wb, rge_Wg);
    k_rowcol_ent<<<Bc * Mv, 256>>>(ent_hs, mirror);
    k_gemm1<<<dim3(6, Bc * Mv), 512, DSMEM>>>(rel_hs, rel_out, egr_beta, egr_gamma);
    k_rowcol_rel<<<Bc * Mv, 256>>>(rel_out);
    k_cond2<<<dim3((Sv + 127) / 128, Bc), 256>>>(lam, upper);
    k_gemm2<<<dim3(6, BSv / 128), 512, DSMEM>>>(ent_hs, ent_out, rge_beta, rge_gamma);
}

// round 8
// speedup vs baseline: 3.6143x; 1.5956x over previous
#include <cuda_runtime.h>
#include <cuda_fp16.h>
#include <cstdint>

constexpr int Bc = 4;
constexpr int Mv = 128;
constexpr int Ev = 768;
constexpr int Rv = 768;
constexpr int Sv = Mv * (Mv + 1) / 2;   // 8256
constexpr int BSv = Bc * Sv;            // 33024

// ---------------- device scratch ----------------
__device__ float g_erow[Bc * Ev * Mv];     // [b][e][i]
__device__ float g_ecol[Bc * Ev * Mv];     // [b][e][j]
__device__ float g_rrow[Bc * Rv * Mv];
__device__ float g_rcol[Bc * Rv * Mv];
__device__ float g_mean_rel[Bc * Mv * Mv];
__device__ float g_rstd_rel[Bc * Mv * Mv];
__device__ float g_mean_ent[BSv];
__device__ float g_rstd_ent[BSv];
__device__ float g_alT[Mv * Ev];
__device__ float g_beT[Mv * Ev];
__device__ float g_ralT[Mv * Rv];
__device__ float g_rbeT[Mv * Rv];
__device__ __half g_cDh[(size_t)BSv * Rv];             // cond fp16
__device__ __half g_W1h[1536 * 768];                   // rows 0..767 egr_Wb, 768..1535 egr_Wg
__device__ __half g_W2h[1536 * 768];                   // rows 0..767 rge_Wb, 768..1535 rge_Wg

// ---------------- PTX helpers (baseline-target only) ----------------
__device__ __forceinline__ uint32_t s2u(const void* p) {
    uint32_t a;
    asm("{ .reg .u64 t; cvta.to.shared.u64 t, %1; cvt.u32.u64 %0, t; }" : "=r"(a) : "l"(p));
    return a;
}
__device__ __forceinline__ void ldsm_x4(uint32_t r[4], uint32_t a) {
    asm volatile("ldmatrix.sync.aligned.m8n8.x4.shared.b16 {%0,%1,%2,%3}, [%4];"
        : "=r"(r[0]), "=r"(r[1]), "=r"(r[2]), "=r"(r[3]) : "r"(a));
}
__device__ __forceinline__ void mma16816(float c[4], const uint32_t a[4], const uint32_t b[2]) {
    asm volatile("mma.sync.aligned.m16n8k16.row.col.f32.f16.f16.f32 "
        "{%0,%1,%2,%3}, {%4,%5,%6,%7}, {%8,%9}, {%0,%1,%2,%3};"
        : "+f"(c[0]), "+f"(c[1]), "+f"(c[2]), "+f"(c[3])
        : "r"(a[0]), "r"(a[1]), "r"(a[2]), "r"(a[3]), "r"(b[0]), "r"(b[1]));
}
__device__ __forceinline__ void cpa16(uint32_t dst, const void* src) {
    asm volatile("cp.async.cg.shared.global [%0], [%1], 16;" :: "r"(dst), "l"(src));
}
#define CP_COMMIT() asm volatile("cp.async.commit_group;" ::: "memory")
#define CP_WAIT0()  asm volatile("cp.async.wait_group 0;" ::: "memory")

// smem stage layout (bytes), padded stride 72 fp16 = 144B (conflict-free ldmatrix)
constexpr int B_OFF = 18432;           // A: 128*144
constexpr int STGSZ = 18432 + 36864;   // + B: 256*144 = 55296
constexpr int DSMEM = 2 * STGSZ;       // 110592 B

// ---------------- mean / rstd (float4 loads) ----------------
__global__ void k_meanvar(const float* __restrict__ x, int which) {
    int row = blockIdx.x;
    const float4* p = (const float4*)(x + (size_t)row * 768);
    float s = 0.f, ss = 0.f;
    for (int t = threadIdx.x; t < 192; t += 256) {
        float4 v = p[t];
        s += v.x + v.y + v.z + v.w;
        ss = fmaf(v.x, v.x, ss); ss = fmaf(v.y, v.y, ss);
        ss = fmaf(v.z, v.z, ss); ss = fmaf(v.w, v.w, ss);
    }
    #pragma unroll
    for (int o = 16; o; o >>= 1) {
        s  += __shfl_xor_sync(0xffffffffu, s, o);
        ss += __shfl_xor_sync(0xffffffffu, ss, o);
    }
    __shared__ float sm[8], sm2[8];
    int w = threadIdx.x >> 5;
    if ((threadIdx.x & 31) == 0) { sm[w] = s; sm2[w] = ss; }
    __syncthreads();
    if (threadIdx.x == 0) {
        float S = 0.f, SS = 0.f;
        #pragma unroll
        for (int q = 0; q < 8; ++q) { S += sm[q]; SS += sm2[q]; }
        float mean = S * (1.f / 768.f);
        float var  = SS * (1.f / 768.f) - mean * mean;
        float d    = var + 1e-12f;
        float r    = 1.f / (d * d);            // faithful: std = (var+eps)^2
        if (which == 0) { g_mean_rel[row] = mean; g_rstd_rel[row] = r; }
        else            { g_mean_ent[row] = mean; g_rstd_ent[row] = r; }
    }
}

// ---------------- transpose params ----------------
__global__ void k_transpose4(const float* __restrict__ ea, const float* __restrict__ eb,
                             const float* __restrict__ ra, const float* __restrict__ rb) {
    int which = blockIdx.y;
    const float* in = (which == 0) ? ea : (which == 1) ? eb : (which == 2) ? ra : rb;
    float* out = (which == 0) ? g_alT : (which == 1) ? g_beT : (which == 2) ? g_ralT : g_rbeT;
    int idx = blockIdx.x * 256 + threadIdx.x;
    if (idx < Mv * 768) {
        int j = idx / 768;
        int e = idx - j * 768;
        out[idx] = in[e * Mv + j];
    }
}

// ---------------- convert weights to fp16 ----------------
__global__ void k_cvtw(const float* __restrict__ egWb, const float* __restrict__ egWg,
                       const float* __restrict__ rgWb, const float* __restrict__ rgWg) {
    int idx = blockIdx.x * 256 + threadIdx.x;
    if (idx >= 1536 * 768) return;
    int which = blockIdx.y;
    int row = idx / 768, col = idx - row * 768;
    const float* Wb = which ? rgWb : egWb;
    const float* Wg = which ? rgWg : egWg;
    float x = (row < 768) ? Wb[row * 768 + col] : Wg[(row - 768) * 768 + col];
    __half h = __float2half_rn(x);
    if (which) g_W2h[idx] = h;
    else       g_W1h[idx] = h;
}

// ---------------- erow / ecol ----------------
__global__ void k_rowcol_ent(const float* __restrict__ eh, const int* __restrict__ mir) {
    int b = blockIdx.x >> 7, i = blockIdx.x & 127;
    __shared__ int mids[Mv];
    if (threadIdx.x < Mv) mids[threadIdx.x] = mir[i * Mv + threadIdx.x];
    __syncthreads();
    for (int e = threadIdx.x; e < Ev; e += 256) {
        float aR = 0.f, aC = 0.f;
        #pragma unroll 4
        for (int j = 0; j < Mv; ++j) {
            float v = eh[((size_t)b * Sv + mids[j]) * Ev + e];
            aR = fmaf(v, g_alT[j * Ev + e], aR);
            aC = fmaf(v, g_beT[j * Ev + e], aC);
        }
        g_erow[(b * Ev + e) * Mv + i] = aR;
        g_ecol[(b * Ev + e) * Mv + i] = aC;
    }
}

// ---------------- rrow / rcol from rel_guided ----------------
__global__ void k_rowcol_rel(const float* __restrict__ rg) {
    int b = blockIdx.x >> 7, k = blockIdx.x & 127;
    const float* rgb = rg + (size_t)b * Mv * Mv * Rv;
    for (int r = threadIdx.x; r < Rv; r += 256) {
        float aR = 0.f, aC = 0.f;
        const float* prow = rgb + (size_t)k * Mv * Rv + r;
        const float* pcol = rgb + (size_t)k * Rv + r;
        #pragma unroll 4
        for (int j = 0; j < Mv; ++j) {
            aR = fmaf(prow[(size_t)j * Rv], g_ralT[j * Rv + r], aR);
            aC = fmaf(pcol[(size_t)j * Mv * Rv], g_rbeT[j * Rv + r], aC);
        }
        g_rrow[(b * Rv + r) * Mv + k] = aR;
        g_rcol[(b * Rv + r) * Mv + k] = aC;
    }
}

// ---------------- cond[(b,s)][r] -> fp16 ----------------
__global__ void k_cond2(const float* __restrict__ lam, const int* __restrict__ upper) {
    int b = blockIdx.y;
    int s0 = blockIdx.x * 128;
    __shared__ float rrS[32][128], rcS[32][128], lamS[32];
    __shared__ int iS[128], jS[128];
    int tid = threadIdx.x;
    if (tid < 128) {
        int s = s0 + tid;
        if (s < Sv) { int u = upper[s]; iS[tid] = u >> 7; jS[tid] = u & 127; }
        else        { iS[tid] = 0; jS[tid] = 0; }
    }
    int s_loc = tid >> 1, rh = (tid & 1) * 16;
    int s = s0 + s_loc;
    for (int rch = 0; rch < 24; ++rch) {
        int r0 = rch * 32;
        __syncthreads();
        #pragma unroll
        for (int q = 0; q < 16; ++q) {
            int idx = q * 256 + tid;
            int rk = idx >> 7, mm = idx & 127;
            rrS[rk][mm] = g_rrow[((size_t)b * Rv + r0 + rk) * Mv + mm];
            rcS[rk][mm] = g_rcol[((size_t)b * Rv + r0 + rk) * Mv + mm];
        }
        if (tid < 32) lamS[tid] = lam[r0 + tid];
        __syncthreads();
        if (s < Sv) {
            int ii = iS[s_loc], jj = jS[s_loc];
            uint32_t h8[8];
            #pragma unroll
            for (int p = 0; p < 8; ++p) {
                int r = rh + p * 2;
                float l0 = lamS[r], l1 = lamS[r + 1];
                float x0 = l0 * rrS[r][ii] * rcS[r][jj] + (1.f - l0) * rrS[r][jj] * rcS[r][ii];
                float x1 = l1 * rrS[r + 1][ii] * rcS[r + 1][jj] + (1.f - l1) * rrS[r + 1][jj] * rcS[r + 1][ii];
                __half2 h = __float22half2_rn(make_float2(x0, x1));
                h8[p] = *(uint32_t*)&h;
            }
            size_t off = ((size_t)b * Sv + s) * Rv + r0 + rh;
            *(uint4*)(g_cDh + off)     = make_uint4(h8[0], h8[1], h8[2], h8[3]);
            *(uint4*)(g_cDh + off + 8) = make_uint4(h8[4], h8[5], h8[6], h8[7]);
        }
    }
}

// ================= GEMM1: 512-thread pipelined fp16 mma.sync -> rel_guided =================
// CTA m=128 (j) x n=256 (128 r x {Wb,Wg}); 16 warps, warp tile 32x64; K chunks of 64, 2-stage.
__global__ __launch_bounds__(512, 1) void k_gemm1(
    const float* __restrict__ rel_hs, float* __restrict__ rel_out,
    const float* __restrict__ ebeta, const float* __restrict__ egam) {
    extern __shared__ char base[];
    const uint32_t sm0 = s2u(base);

    const int tid = threadIdx.x, w = tid >> 5, L = tid & 31;
    const int r0 = blockIdx.x * 128;
    const int byi = blockIdx.y;                // b*128 + i
    const int b = byi >> 7, i = byi & 127;
    const int m0w = (w >> 2) * 32, n0w = (w & 3) * 64;

    __shared__ float betS[128], gamS[128];
    if (tid < 128) { betS[tid] = ebeta[r0 + tid]; gamS[tid] = egam[r0 + tid]; }

    float acc[2][8][4];
    #pragma unroll
    for (int mt = 0; mt < 2; ++mt)
        #pragma unroll
        for (int nt = 0; nt < 8; ++nt)
            #pragma unroll
            for (int q = 0; q < 4; ++q) acc[mt][nt][q] = 0.f;

    const float* erow_bi = g_erow + (size_t)b * Ev * Mv + i;
    const float* ecol_b  = g_ecol + (size_t)b * Ev * Mv;

    const int jA = tid >> 2, khA = (tid & 3) * 16;   // A construct: row jA, 16 k
    const int bRow = tid >> 3, bSeg = tid & 7;       // B cp.async
    const uint32_t aBase = sm0 + (uint32_t)(m0w + (L & 15)) * 144 + (uint32_t)(L >> 4) * 16;
    const uint32_t bBase = sm0 + B_OFF
        + (uint32_t)(n0w + (L & 7) + ((L >> 4) << 3)) * 144 + (uint32_t)((L >> 3) & 1) * 16;

    auto stageB = [&](int ch, int st) {
        const int k0 = ch * 64;
        uint32_t sB = sm0 + st * STGSZ + B_OFF;
        #pragma unroll
        for (int q = 0; q < 4; ++q) {
            int row = bRow + q * 64;
            int src = r0 + (row >> 1) + (row & 1) * 768;
            cpa16(sB + (uint32_t)row * 144 + bSeg * 16,
                  g_W1h + (size_t)src * 768 + k0 + bSeg * 8);
        }
    };
    auto makeA = [&](int ch, int st) {
        const int k0 = ch * 64;
        char* sb = base + st * STGSZ;
        const float* pe = ecol_b + (size_t)(k0 + khA) * Mv + jA;
        const float* pr = erow_bi + (size_t)(k0 + khA) * Mv;
        char* Ah = sb + (size_t)jA * 144 + khA * 2;
        #pragma unroll
        for (int g = 0; g < 2; ++g) {
            uint32_t h[4];
            #pragma unroll
            for (int p = 0; p < 4; ++p) {
                int kk = g * 8 + p * 2;
                float x0 = pe[(size_t)kk * Mv] * pr[(size_t)kk * Mv];
                float x1 = pe[(size_t)(kk + 1) * Mv] * pr[(size_t)(kk + 1) * Mv];
                __half2 hh = __float22half2_rn(make_float2(x0, x1));
                h[p] = *(uint32_t*)&hh;
            }
            *(uint4*)(Ah + g * 16) = make_uint4(h[0], h[1], h[2], h[3]);
        }
    };

    stageB(0, 0);
    CP_COMMIT();
    makeA(0, 0);

    for (int ch = 0; ch < 12; ++ch) {
        const int cur = ch & 1, nxt = cur ^ 1;
        CP_WAIT0();
        __syncthreads();
        if (ch < 11) {
            stageB(ch + 1, nxt);
            CP_COMMIT();
            makeA(ch + 1, nxt);
        }
        const uint32_t aA = aBase + cur * STGSZ;
        const uint32_t bA = bBase + cur * STGSZ;
        #pragma unroll
        for (int ks = 0; ks < 64; ks += 16) {
            uint32_t ah[2][4];
            #pragma unroll
            for (int mt = 0; mt < 2; ++mt)
                ldsm_x4(ah[mt], aA + mt * 2304 + ks * 2);
            #pragma unroll
            for (int np = 0; np < 4; ++np) {
                uint32_t bh[4];
                ldsm_x4(bh, bA + np * 2304 + ks * 2);
                #pragma unroll
                for (int mt = 0; mt < 2; ++mt) {
                    mma16816(acc[mt][2 * np],     ah[mt], bh);
                    mma16816(acc[mt][2 * np + 1], ah[mt], bh + 2);
                }
            }
        }
    }

    // epilogue
    const int gid = L >> 2, tig = L & 3;
    #pragma unroll
    for (int mt = 0; mt < 2; ++mt) {
        int j1 = m0w + mt * 16 + gid;
        int row1 = byi * 128 + j1, row2 = row1 + 8;
        float mn1 = g_mean_rel[row1], rs1 = g_rstd_rel[row1];
        float mn2 = g_mean_rel[row2], rs2 = g_rstd_rel[row2];
        const float* x1 = rel_hs + (size_t)row1 * 768;
        const float* x2 = rel_hs + (size_t)row2 * 768;
        float* o1 = rel_out + (size_t)row1 * 768;
        float* o2 = rel_out + (size_t)row2 * 768;
        #pragma unroll
        for (int nt = 0; nt < 8; ++nt) {
            int rl = (n0w >> 1) + nt * 4 + tig;
            int r = r0 + rl;
            const float* c = acc[mt][nt];
            o1[r] = (x1[r] - mn1) * rs1 * (c[1] + gamS[rl]) + c[0] + betS[rl];
            o2[r] = (x2[r] - mn2) * rs2 * (c[3] + gamS[rl]) + c[2] + betS[rl];
        }
    }
}

// ================= GEMM2: 512-thread pipelined fp16 (pure cp.async) -> ent_guided =================
__global__ __launch_bounds__(512, 1) void k_gemm2(
    const float* __restrict__ ent_hs, float* __restrict__ ent_out,
    const float* __restrict__ rbeta, const float* __restrict__ rgam) {
    extern __shared__ char base[];
    const uint32_t sm0 = s2u(base);

    const int tid = threadIdx.x, w = tid >> 5, L = tid & 31;
    const int e0 = blockIdx.x * 128;
    const int m0 = blockIdx.y * 128;
    const int m0w = (w >> 2) * 32, n0w = (w & 3) * 64;

    __shared__ float betS[128], gamS[128];
    if (tid < 128) { betS[tid] = rbeta[e0 + tid]; gamS[tid] = rgam[e0 + tid]; }

    float acc[2][8][4];
    #pragma unroll
    for (int mt = 0; mt < 2; ++mt)
        #pragma unroll
        for (int nt = 0; nt < 8; ++nt)
            #pragma unroll
            for (int q = 0; q < 4; ++q) acc[mt][nt][q] = 0.f;

    const int cRow = tid >> 3, cSeg = tid & 7;
    const uint32_t aBase = sm0 + (uint32_t)(m0w + (L & 15)) * 144 + (uint32_t)(L >> 4) * 16;
    const uint32_t bBase = sm0 + B_OFF
        + (uint32_t)(n0w + (L & 7) + ((L >> 4) << 3)) * 144 + (uint32_t)((L >> 3) & 1) * 16;

    auto stage = [&](int ch, int st) {
        const int k0 = ch * 64;
        uint32_t sA = sm0 + st * STGSZ;
        #pragma unroll
        for (int q = 0; q < 2; ++q) {
            int row = cRow + q * 64;
            cpa16(sA + (uint32_t)row * 144 + cSeg * 16,
                  g_cDh + (size_t)(m0 + row) * Rv + k0 + cSeg * 8);
        }
        #pragma unroll
        for (int q = 0; q < 4; ++q) {
            int row = cRow + q * 64;
            int src = e0 + (row >> 1) + (row & 1) * 768;
            cpa16(sA + B_OFF + (uint32_t)row * 144 + cSeg * 16,
                  g_W2h + (size_t)src * 768 + k0 + cSeg * 8);
        }
    };

    stage(0, 0);
    CP_COMMIT();

    for (int ch = 0; ch < 12; ++ch) {
        const int cur = ch & 1, nxt = cur ^ 1;
        CP_WAIT0();
        __syncthreads();
        if (ch < 11) {
            stage(ch + 1, nxt);
            CP_COMMIT();
        }
        const uint32_t aA = aBase + cur * STGSZ;
        const uint32_t bA = bBase + cur * STGSZ;
        #pragma unroll
        for (int ks = 0; ks < 64; ks += 16) {
            uint32_t ah[2][4];
            #pragma unroll
            for (int mt = 0; mt < 2; ++mt)
                ldsm_x4(ah[mt], aA + mt * 2304 + ks * 2);
            #pragma unroll
            for (int np = 0; np < 4; ++np) {
                uint32_t bh[4];
                ldsm_x4(bh, bA + np * 2304 + ks * 2);
                #pragma unroll
                for (int mt = 0; mt < 2; ++mt) {
                    mma16816(acc[mt][2 * np],     ah[mt], bh);
                    mma16816(acc[mt][2 * np + 1], ah[mt], bh + 2);
                }
            }
        }
    }

    const int gid = L >> 2, tig = L & 3;
    #pragma unroll
    for (int mt = 0; mt < 2; ++mt) {
        int row1 = m0 + m0w + mt * 16 + gid, row2 = row1 + 8;
        float mn1 = g_mean_ent[row1], rs1 = g_rstd_ent[row1];
        float mn2 = g_mean_ent[row2], rs2 = g_rstd_ent[row2];
        const float* x1 = ent_hs + (size_t)row1 * 768;
        const float* x2 = ent_hs + (size_t)row2 * 768;
        float* o1 = ent_out + (size_t)row1 * 768;
        float* o2 = ent_out + (size_t)row2 * 768;
        #pragma unroll
        for (int nt = 0; nt < 8; ++nt) {
            int el = (n0w >> 1) + nt * 4 + tig;
            int e = e0 + el;
            const float* c = acc[mt][nt];
            o1[e] = (x1[e] - mn1) * rs1 * (c[1] + gamS[el]) + c[0] + betS[el];
            o2[e] = (x2[e] - mn2) * rs2 * (c[3] + gamS[el]) + c[2] + betS[el];
        }
    }
}

// ---------------- launch ----------------
extern "C" void kernel_launch(void* const* d_in, const int* in_sizes, int n_in,
                              void* d_out, int out_size) {
    const float* ent_hs    = (const float*)d_in[0];
    const float* rel_hs    = (const float*)d_in[1];
    const float* ent_alpha = (const float*)d_in[2];
    const float* ent_beta  = (const float*)d_in[3];
    const float* rel_alpha = (const float*)d_in[4];
    const float* rel_beta  = (const float*)d_in[5];
    const float* lam       = (const float*)d_in[6];
    const float* egr_Wb    = (const float*)d_in[7];
    const float* egr_Wg    = (const float*)d_in[8];
    const float* egr_beta  = (const float*)d_in[9];
    const float* egr_gamma = (const float*)d_in[10];
    const float* rge_Wb    = (const float*)d_in[11];
    const float* rge_Wg    = (const float*)d_in[12];
    const float* rge_beta  = (const float*)d_in[13];
    const float* rge_gamma = (const float*)d_in[14];
    const int*   mirror    = (const int*)d_in[15];
    const int*   upper     = (const int*)d_in[16];

    float* ent_out = (float*)d_out;                              // [B,S,E]
    float* rel_out = (float*)d_out + (size_t)Bc * Sv * Ev;       // [B,M,M,R]

    cudaFuncSetAttribute(k_gemm1, cudaFuncAttributeMaxDynamicSharedMemorySize, DSMEM);
    cudaFuncSetAttribute(k_gemm2, cudaFuncAttributeMaxDynamicSharedMemorySize, DSMEM);

    k_meanvar<<<Bc * Mv * Mv, 256>>>(rel_hs, 0);
    k_meanvar<<<BSv, 256>>>(ent_hs, 1);
    k_transpose4<<<dim3((Mv * 768 + 255) / 256, 4), 256>>>(ent_alpha, ent_beta, rel_alpha, rel_beta);
    k_cvtw<<<dim3((1536 * 768 + 255) / 256, 2), 256>>>(egr_Wb, egr_Wg, rge_Wb, rge_Wg);
    k_rowcol_ent<<<Bc * Mv, 256>>>(ent_hs, mirror);
    k_gemm1<<<dim3(6, Bc * Mv), 512, DSMEM>>>(rel_hs, rel_out, egr_beta, egr_gamma);
    k_rowcol_rel<<<Bc * Mv, 256>>>(rel_out);
    k_cond2<<<dim3((Sv + 127) / 128, Bc), 256>>>(lam, upper);
    k_gemm2<<<dim3(6, BSv / 128), 512, DSMEM>>>(ent_hs, ent_out, rge_beta, rge_gamma);
}

// round 9
// speedup vs baseline: 3.7865x; 1.0476x over previous
#include <cuda_runtime.h>
#include <cuda_fp16.h>
#include <cstdint>

constexpr int Bc = 4;
constexpr int Mv = 128;
constexpr int Ev = 768;
constexpr int Rv = 768;
constexpr int Sv = Mv * (Mv + 1) / 2;   // 8256
constexpr int BSv = Bc * Sv;            // 33024

// ---------------- device scratch ----------------
__device__ float g_erow[Bc * Mv * Ev];     // [b][i][e]  (layout for coalesced k_actx reads)
__device__ float g_ecol[Bc * Ev * Mv];     // [b][e][j]
__device__ float g_rrow[Bc * Rv * Mv];
__device__ float g_rcol[Bc * Rv * Mv];
__device__ float g_mean_rel[Bc * Mv * Mv];
__device__ float g_rstd_rel[Bc * Mv * Mv];
__device__ float g_mean_ent[BSv];
__device__ float g_rstd_ent[BSv];
__device__ float g_alT[Mv * Ev];
__device__ float g_beT[Mv * Ev];
__device__ float g_ralT[Mv * Rv];
__device__ float g_rbeT[Mv * Rv];
__device__ __half g_cDh[(size_t)BSv * Rv];             // cond fp16
__device__ __half g_A1[(size_t)Bc * Mv * Mv * Ev];     // ent_ctx fp16 [byi][j][e]
__device__ __half g_W1h[1536 * 768];                   // rows 0..767 egr_Wb, 768..1535 egr_Wg
__device__ __half g_W2h[1536 * 768];                   // rows 0..767 rge_Wb, 768..1535 rge_Wg

// ---------------- PTX helpers (baseline-target only) ----------------
__device__ __forceinline__ uint32_t s2u(const void* p) {
    uint32_t a;
    asm("{ .reg .u64 t; cvta.to.shared.u64 t, %1; cvt.u32.u64 %0, t; }" : "=r"(a) : "l"(p));
    return a;
}
__device__ __forceinline__ void ldsm_x4(uint32_t r[4], uint32_t a) {
    asm volatile("ldmatrix.sync.aligned.m8n8.x4.shared.b16 {%0,%1,%2,%3}, [%4];"
        : "=r"(r[0]), "=r"(r[1]), "=r"(r[2]), "=r"(r[3]) : "r"(a));
}
__device__ __forceinline__ void mma16816(float c[4], const uint32_t a[4], const uint32_t b[2]) {
    asm volatile("mma.sync.aligned.m16n8k16.row.col.f32.f16.f16.f32 "
        "{%0,%1,%2,%3}, {%4,%5,%6,%7}, {%8,%9}, {%0,%1,%2,%3};"
        : "+f"(c[0]), "+f"(c[1]), "+f"(c[2]), "+f"(c[3])
        : "r"(a[0]), "r"(a[1]), "r"(a[2]), "r"(a[3]), "r"(b[0]), "r"(b[1]));
}
__device__ __forceinline__ void cpa16(uint32_t dst, const void* src) {
    asm volatile("cp.async.cg.shared.global [%0], [%1], 16;" :: "r"(dst), "l"(src));
}
#define CP_COMMIT() asm volatile("cp.async.commit_group;" ::: "memory")
#define CP_WAIT0()  asm volatile("cp.async.wait_group 0;" ::: "memory")
#define CP_WAIT1()  asm volatile("cp.async.wait_group 1;" ::: "memory")

// smem stage layout (bytes), padded stride 72 fp16 = 144B (conflict-free ldmatrix)
constexpr int B_OFF = 18432;           // A: 128*144
constexpr int STGSZ = 18432 + 36864;   // + B: 256*144 = 55296
constexpr int NSTG  = 3;
constexpr int DSMEM = NSTG * STGSZ;    // 165888 B (epilogue reuses 67584 of it)

// ---------------- mean / rstd (float4 loads) ----------------
__global__ void k_meanvar(const float* __restrict__ x, int which) {
    int row = blockIdx.x;
    const float4* p = (const float4*)(x + (size_t)row * 768);
    float s = 0.f, ss = 0.f;
    for (int t = threadIdx.x; t < 192; t += 256) {
        float4 v = p[t];
        s += v.x + v.y + v.z + v.w;
        ss = fmaf(v.x, v.x, ss); ss = fmaf(v.y, v.y, ss);
        ss = fmaf(v.z, v.z, ss); ss = fmaf(v.w, v.w, ss);
    }
    #pragma unroll
    for (int o = 16; o; o >>= 1) {
        s  += __shfl_xor_sync(0xffffffffu, s, o);
        ss += __shfl_xor_sync(0xffffffffu, ss, o);
    }
    __shared__ float sm[8], sm2[8];
    int w = threadIdx.x >> 5;
    if ((threadIdx.x & 31) == 0) { sm[w] = s; sm2[w] = ss; }
    __syncthreads();
    if (threadIdx.x == 0) {
        float S = 0.f, SS = 0.f;
        #pragma unroll
        for (int q = 0; q < 8; ++q) { S += sm[q]; SS += sm2[q]; }
        float mean = S * (1.f / 768.f);
        float var  = SS * (1.f / 768.f) - mean * mean;
        float d    = var + 1e-12f;
        float r    = 1.f / (d * d);            // faithful: std = (var+eps)^2
        if (which == 0) { g_mean_rel[row] = mean; g_rstd_rel[row] = r; }
        else            { g_mean_ent[row] = mean; g_rstd_ent[row] = r; }
    }
}

// ---------------- transpose params ----------------
__global__ void k_transpose4(const float* __restrict__ ea, const float* __restrict__ eb,
                             const float* __restrict__ ra, const float* __restrict__ rb) {
    int which = blockIdx.y;
    const float* in = (which == 0) ? ea : (which == 1) ? eb : (which == 2) ? ra : rb;
    float* out = (which == 0) ? g_alT : (which == 1) ? g_beT : (which == 2) ? g_ralT : g_rbeT;
    int idx = blockIdx.x * 256 + threadIdx.x;
    if (idx < Mv * 768) {
        int j = idx / 768;
        int e = idx - j * 768;
        out[idx] = in[e * Mv + j];
    }
}

// ---------------- convert weights to fp16 ----------------
__global__ void k_cvtw(const float* __restrict__ egWb, const float* __restrict__ egWg,
                       const float* __restrict__ rgWb, const float* __restrict__ rgWg) {
    int idx = blockIdx.x * 256 + threadIdx.x;
    if (idx >= 1536 * 768) return;
    int which = blockIdx.y;
    int row = idx / 768, col = idx - row * 768;
    const float* Wb = which ? rgWb : egWb;
    const float* Wg = which ? rgWg : egWg;
    float x = (row < 768) ? Wb[row * 768 + col] : Wg[(row - 768) * 768 + col];
    __half h = __float2half_rn(x);
    if (which) g_W2h[idx] = h;
    else       g_W1h[idx] = h;
}

// ---------------- erow / ecol ----------------
__global__ void k_rowcol_ent(const float* __restrict__ eh, const int* __restrict__ mir) {
    int b = blockIdx.x >> 7, i = blockIdx.x & 127;
    __shared__ int mids[Mv];
    if (threadIdx.x < Mv) mids[threadIdx.x] = mir[i * Mv + threadIdx.x];
    __syncthreads();
    for (int e = threadIdx.x; e < Ev; e += 256) {
        float aR = 0.f, aC = 0.f;
        #pragma unroll 4
        for (int j = 0; j < Mv; ++j) {
            float v = eh[((size_t)b * Sv + mids[j]) * Ev + e];
            aR = fmaf(v, g_alT[j * Ev + e], aR);
            aC = fmaf(v, g_beT[j * Ev + e], aC);
        }
        g_erow[((size_t)b * Mv + i) * Ev + e] = aR;     // [b][i][e]
        g_ecol[((size_t)b * Ev + e) * Mv + i] = aC;     // [b][e][j]
    }
}

// ---------------- materialize ent_ctx fp16: g_A1[byi][j][e] ----------------
__global__ void k_actx() {
    int byi = blockIdx.x;              // b*128 + i
    int b = byi >> 7;
    __shared__ float er[768];
    __shared__ float S[32][129];
    int tid = threadIdx.x;
    #pragma unroll
    for (int q = 0; q < 3; ++q) er[q * 256 + tid] = g_erow[(size_t)byi * Ev + q * 256 + tid];
    for (int t = 0; t < 24; ++t) {
        int e0 = t * 32;
        __syncthreads();
        #pragma unroll
        for (int q = 0; q < 16; ++q) {
            int idx = q * 256 + tid;
            int e = idx >> 7, j = idx & 127;
            S[e][j] = g_ecol[((size_t)b * Ev + e0 + e) * Mv + j];
        }
        __syncthreads();
        int j = tid >> 1, h = tid & 1;
        uint32_t hh[8];
        #pragma unroll
        for (int p = 0; p < 8; ++p) {
            int e = h * 16 + p * 2;
            float x0 = er[e0 + e]     * S[e][j];
            float x1 = er[e0 + e + 1] * S[e + 1][j];
            __half2 v = __float22half2_rn(make_float2(x0, x1));
            hh[p] = *(uint32_t*)&v;
        }
        __half* dst = g_A1 + ((size_t)byi * 128 + j) * 768 + e0 + h * 16;
        *(uint4*)(dst)     = make_uint4(hh[0], hh[1], hh[2], hh[3]);
        *(uint4*)(dst + 8) = make_uint4(hh[4], hh[5], hh[6], hh[7]);
    }
}

// ---------------- rrow / rcol from rel_guided ----------------
__global__ void k_rowcol_rel(const float* __restrict__ rg) {
    int b = blockIdx.x >> 7, k = blockIdx.x & 127;
    const float* rgb = rg + (size_t)b * Mv * Mv * Rv;
    for (int r = threadIdx.x; r < Rv; r += 256) {
        float aR = 0.f, aC = 0.f;
        const float* prow = rgb + (size_t)k * Mv * Rv + r;
        const float* pcol = rgb + (size_t)k * Rv + r;
        #pragma unroll 4
        for (int j = 0; j < Mv; ++j) {
            aR = fmaf(prow[(size_t)j * Rv], g_ralT[j * Rv + r], aR);
            aC = fmaf(pcol[(size_t)j * Mv * Rv], g_rbeT[j * Rv + r], aC);
        }
        g_rrow[(b * Rv + r) * Mv + k] = aR;
        g_rcol[(b * Rv + r) * Mv + k] = aC;
    }
}

// ---------------- cond[(b,s)][r] -> fp16 ----------------
__global__ void k_cond2(const float* __restrict__ lam, const int* __restrict__ upper) {
    int b = blockIdx.y;
    int s0 = blockIdx.x * 128;
    __shared__ float rrS[32][128], rcS[32][128], lamS[32];
    __shared__ int iS[128], jS[128];
    int tid = threadIdx.x;
    if (tid < 128) {
        int s = s0 + tid;
        if (s < Sv) { int u = upper[s]; iS[tid] = u >> 7; jS[tid] = u & 127; }
        else        { iS[tid] = 0; jS[tid] = 0; }
    }
    int s_loc = tid >> 1, rh = (tid & 1) * 16;
    int s = s0 + s_loc;
    for (int rch = 0; rch < 24; ++rch) {
        int r0 = rch * 32;
        __syncthreads();
        #pragma unroll
        for (int q = 0; q < 16; ++q) {
            int idx = q * 256 + tid;
            int rk = idx >> 7, mm = idx & 127;
            rrS[rk][mm] = g_rrow[((size_t)b * Rv + r0 + rk) * Mv + mm];
            rcS[rk][mm] = g_rcol[((size_t)b * Rv + r0 + rk) * Mv + mm];
        }
        if (tid < 32) lamS[tid] = lam[r0 + tid];
        __syncthreads();
        if (s < Sv) {
            int ii = iS[s_loc], jj = jS[s_loc];
            uint32_t h8[8];
            #pragma unroll
            for (int p = 0; p < 8; ++p) {
                int r = rh + p * 2;
                float l0 = lamS[r], l1 = lamS[r + 1];
                float x0 = l0 * rrS[r][ii] * rcS[r][jj] + (1.f - l0) * rrS[r][jj] * rcS[r][ii];
                float x1 = l1 * rrS[r + 1][ii] * rcS[r + 1][jj] + (1.f - l1) * rrS[r + 1][jj] * rcS[r + 1][ii];
                __half2 h = __float22half2_rn(make_float2(x0, x1));
                h8[p] = *(uint32_t*)&h;
            }
            size_t off = ((size_t)b * Sv + s) * Rv + r0 + rh;
            *(uint4*)(g_cDh + off)     = make_uint4(h8[0], h8[1], h8[2], h8[3]);
            *(uint4*)(g_cDh + off + 8) = make_uint4(h8[4], h8[5], h8[6], h8[7]);
        }
    }
}

// ================= generic fp16 GEMM + CLN body (pure cp.async, 3-stage) =================
// CTA m=128 x n=256 (128 out-cols x {Wb,Wg} interleaved); 16 warps, warp tile 32x64.
template <typename StageF>
__device__ __forceinline__ void gemm_body(
    char* base, uint32_t sm0, int tid, int w, int L,
    StageF stage,
    const float* x_src, float* x_dst, size_t row_base, int col0,
    const float* mS, const float* sS, const float* betS, const float* gamS) {
    const int m0w = (w >> 2) * 32, n0w = (w & 3) * 64;

    float acc[2][8][4];
    #pragma unroll
    for (int mt = 0; mt < 2; ++mt)
        #pragma unroll
        for (int nt = 0; nt < 8; ++nt)
            #pragma unroll
            for (int q = 0; q < 4; ++q) acc[mt][nt][q] = 0.f;

    const uint32_t aBase = sm0 + (uint32_t)(m0w + (L & 15)) * 144 + (uint32_t)(L >> 4) * 16;
    const uint32_t bBase = sm0 + B_OFF
        + (uint32_t)(n0w + (L & 7) + ((L >> 4) << 3)) * 144 + (uint32_t)((L >> 3) & 1) * 16;

    stage(0, 0); CP_COMMIT();
    stage(1, 1); CP_COMMIT();

    int st_nxt = 2;
    for (int ch = 0; ch < 12; ++ch) {
        if (ch == 11) { CP_WAIT0(); } else { CP_WAIT1(); }
        __syncthreads();
        if (ch < 10) {
            stage(ch + 2, st_nxt);
            CP_COMMIT();
            if (++st_nxt == NSTG) st_nxt = 0;
        }
        const uint32_t off = (uint32_t)((ch % NSTG) * STGSZ);
        const uint32_t aA = aBase + off, bA = bBase + off;
        #pragma unroll
        for (int ks = 0; ks < 64; ks += 16) {
            uint32_t ah[2][4];
            #pragma unroll
            for (int mt = 0; mt < 2; ++mt)
                ldsm_x4(ah[mt], aA + mt * 2304 + ks * 2);
            #pragma unroll
            for (int np = 0; np < 4; ++np) {
                uint32_t bh[4];
                ldsm_x4(bh, bA + np * 2304 + ks * 2);
                #pragma unroll
                for (int mt = 0; mt < 2; ++mt) {
                    mma16816(acc[mt][2 * np],     ah[mt], bh);
                    mma16816(acc[mt][2 * np + 1], ah[mt], bh + 2);
                }
            }
        }
    }

    // ---- coalesced smem-staged epilogue ----
    __syncthreads();
    float* XS = (float*)base;                       // [128][132]
    {
        const float* src = x_src + row_base * 768 + col0;
        int j = tid >> 2, c0 = (tid & 3) * 32;
        #pragma unroll
        for (int q = 0; q < 8; ++q)
            *(float4*)(XS + j * 132 + c0 + q * 4) = *(const float4*)(src + (size_t)j * 768 + c0 + q * 4);
    }
    __syncthreads();
    const int gid = L >> 2, tig = L & 3;
    #pragma unroll
    for (int mt = 0; mt < 2; ++mt) {
        int j1 = m0w + mt * 16 + gid, j2 = j1 + 8;
        float mn1 = mS[j1], rs1 = sS[j1], mn2 = mS[j2], rs2 = sS[j2];
        #pragma unroll
        for (int nt = 0; nt < 8; ++nt) {
            int rl = (n0w >> 1) + nt * 4 + tig;
            const float* c = acc[mt][nt];
            float x1 = XS[j1 * 132 + rl], x2 = XS[j2 * 132 + rl];
            XS[j1 * 132 + rl] = (x1 - mn1) * rs1 * (c[1] + gamS[rl]) + c[0] + betS[rl];
            XS[j2 * 132 + rl] = (x2 - mn2) * rs2 * (c[3] + gamS[rl]) + c[2] + betS[rl];
        }
    }
    __syncthreads();
    {
        float* dst = x_dst + row_base * 768 + col0;
        int j = tid >> 2, c0 = (tid & 3) * 32;
        #pragma unroll
        for (int q = 0; q < 8; ++q)
            *(float4*)(dst + (size_t)j * 768 + c0 + q * 4) = *(const float4*)(XS + j * 132 + c0 + q * 4);
    }
}

// ================= GEMM1 -> rel_guided =================
__global__ __launch_bounds__(512, 1) void k_gemm1(
    const float* __restrict__ rel_hs, float* __restrict__ rel_out,
    const float* __restrict__ ebeta, const float* __restrict__ egam) {
    extern __shared__ char base[];
    const uint32_t sm0 = s2u(base);
    const int tid = threadIdx.x, w = tid >> 5, L = tid & 31;
    const int r0 = blockIdx.x * 128;
    const int byi = blockIdx.y;

    __shared__ float betS[128], gamS[128], mS[128], sS[128];
    if (tid < 128) {
        betS[tid] = ebeta[r0 + tid];
        gamS[tid] = egam[r0 + tid];
        mS[tid] = g_mean_rel[byi * 128 + tid];
        sS[tid] = g_rstd_rel[byi * 128 + tid];
    }

    const int cRow = tid >> 3, cSeg = tid & 7;
    auto stage = [&](int ch, int st) {
        const int k0 = ch * 64;
        uint32_t s = sm0 + (uint32_t)(st * STGSZ);
        #pragma unroll
        for (int q = 0; q < 2; ++q) {
            int row = cRow + q * 64;
            cpa16(s + (uint32_t)row * 144 + cSeg * 16,
                  g_A1 + ((size_t)byi * 128 + row) * 768 + k0 + cSeg * 8);
        }
        #pragma unroll
        for (int q = 0; q < 4; ++q) {
            int row = cRow + q * 64;
            int src = r0 + (row >> 1) + (row & 1) * 768;
            cpa16(s + B_OFF + (uint32_t)row * 144 + cSeg * 16,
                  g_W1h + (size_t)src * 768 + k0 + cSeg * 8);
        }
    };

    gemm_body(base, sm0, tid, w, L, stage,
              rel_hs, rel_out, (size_t)byi * 128, r0, mS, sS, betS, gamS);
}

// ================= GEMM2 -> ent_guided =================
__global__ __launch_bounds__(512, 1) void k_gemm2(
    const float* __restrict__ ent_hs, float* __restrict__ ent_out,
    const float* __restrict__ rbeta, const float* __restrict__ rgam) {
    extern __shared__ char base[];
    const uint32_t sm0 = s2u(base);
    const int tid = threadIdx.x, w = tid >> 5, L = tid & 31;
    const int e0 = blockIdx.x * 128;
    const int m0 = blockIdx.y * 128;

    __shared__ float betS[128], gamS[128], mS[128], sS[128];
    if (tid < 128) {
        betS[tid] = rbeta[e0 + tid];
        gamS[tid] = rgam[e0 + tid];
        mS[tid] = g_mean_ent[m0 + tid];
        sS[tid] = g_rstd_ent[m0 + tid];
    }

    const int cRow = tid >> 3, cSeg = tid & 7;
    auto stage = [&](int ch, int st) {
        const int k0 = ch * 64;
        uint32_t s = sm0 + (uint32_t)(st * STGSZ);
        #pragma unroll
        for (int q = 0; q < 2; ++q) {
            int row = cRow + q * 64;
            cpa16(s + (uint32_t)row * 144 + cSeg * 16,
                  g_cDh + (size_t)(m0 + row) * Rv + k0 + cSeg * 8);
        }
        #pragma unroll
        for (int q = 0; q < 4; ++q) {
            int row = cRow + q * 64;
            int src = e0 + (row >> 1) + (row & 1) * 768;
            cpa16(s + B_OFF + (uint32_t)row * 144 + cSeg * 16,
                  g_W2h + (size_t)src * 768 + k0 + cSeg * 8);
        }
    };

    gemm_body(base, sm0, tid, w, L, stage,
              ent_hs, ent_out, (size_t)m0, e0, mS, sS, betS, gamS);
}

// ---------------- launch ----------------
extern "C" void kernel_launch(void* const* d_in, const int* in_sizes, int n_in,
                              void* d_out, int out_size) {
    const float* ent_hs    = (const float*)d_in[0];
    const float* rel_hs    = (const float*)d_in[1];
    const float* ent_alpha = (const float*)d_in[2];
    const float* ent_beta  = (const float*)d_in[3];
    const float* rel_alpha = (const float*)d_in[4];
    const float* rel_beta  = (const float*)d_in[5];
    const float* lam       = (const float*)d_in[6];
    const float* egr_Wb    = (const float*)d_in[7];
    const float* egr_Wg    = (const float*)d_in[8];
    const float* egr_beta  = (const float*)d_in[9];
    const float* egr_gamma = (const float*)d_in[10];
    const float* rge_Wb    = (const float*)d_in[11];
    const float* rge_Wg    = (const float*)d_in[12];
    const float* rge_beta  = (const float*)d_in[13];
    const float* rge_gamma = (const float*)d_in[14];
    const int*   mirror    = (const int*)d_in[15];
    const int*   upper     = (const int*)d_in[16];

    float* ent_out = (float*)d_out;                              // [B,S,E]
    float* rel_out = (float*)d_out + (size_t)Bc * Sv * Ev;       // [B,M,M,R]

    cudaFuncSetAttribute(k_gemm1, cudaFuncAttributeMaxDynamicSharedMemorySize, DSMEM);
    cudaFuncSetAttribute(k_gemm2, cudaFuncAttributeMaxDynamicSharedMemorySize, DSMEM);

    k_meanvar<<<Bc * Mv * Mv, 256>>>(rel_hs, 0);
    k_meanvar<<<BSv, 256>>>(ent_hs, 1);
    k_transpose4<<<dim3((Mv * 768 + 255) / 256, 4), 256>>>(ent_alpha, ent_beta, rel_alpha, rel_beta);
    k_cvtw<<<dim3((1536 * 768 + 255) / 256, 2), 256>>>(egr_Wb, egr_Wg, rge_Wb, rge_Wg);
    k_rowcol_ent<<<Bc * Mv, 256>>>(ent_hs, mirror);
    k_actx<<<Bc * Mv, 256>>>();
    k_gemm1<<<dim3(6, Bc * Mv), 512, DSMEM>>>(rel_hs, rel_out, egr_beta, egr_gamma);
    k_rowcol_rel<<<Bc * Mv, 256>>>(rel_out);
    k_cond2<<<dim3((Sv + 127) / 128, Bc), 256>>>(lam, upper);
    k_gemm2<<<dim3(6, BSv / 128), 512, DSMEM>>>(ent_hs, ent_out, rge_beta, rge_gamma);
}

// round 10
// speedup vs baseline: 4.3605x; 1.1516x over previous
#include <cuda_runtime.h>
#include <cuda_fp16.h>
#include <cstdint>

constexpr int Bc = 4;
constexpr int Mv = 128;
constexpr int Ev = 768;
constexpr int Rv = 768;
constexpr int Sv = Mv * (Mv + 1) / 2;   // 8256
constexpr int BSv = Bc * Sv;            // 33024

// ---------------- device scratch ----------------
__device__ float g_erow[Bc * Mv * Ev];     // [b][i][e]
__device__ float g_ecol[Bc * Ev * Mv];     // [b][e][j]
__device__ float g_rrow[Bc * Rv * Mv];
__device__ float g_rcol[Bc * Rv * Mv];
__device__ float g_mean_rel[Bc * Mv * Mv];
__device__ float g_rstd_rel[Bc * Mv * Mv];
__device__ float g_mean_ent[BSv];
__device__ float g_rstd_ent[BSv];
__device__ float g_alT[Mv * Ev];
__device__ float g_beT[Mv * Ev];
__device__ float g_ralT[Mv * Rv];
__device__ float g_rbeT[Mv * Rv];
__device__ __half g_cDh[(size_t)BSv * Rv];             // cond fp16
__device__ __half g_A1[(size_t)Bc * Mv * Mv * Ev];     // ent_ctx fp16 [byi][j][e]
__device__ __half g_W1h[1536 * 768];                   // rows 0..767 egr_Wb, 768..1535 egr_Wg
__device__ __half g_W2h[1536 * 768];                   // rows 0..767 rge_Wb, 768..1535 rge_Wg

// ---------------- PTX helpers (baseline-target only) ----------------
__device__ __forceinline__ uint32_t s2u(const void* p) {
    uint32_t a;
    asm("{ .reg .u64 t; cvta.to.shared.u64 t, %1; cvt.u32.u64 %0, t; }" : "=r"(a) : "l"(p));
    return a;
}
__device__ __forceinline__ void ldsm_x4(uint32_t r[4], uint32_t a) {
    asm volatile("ldmatrix.sync.aligned.m8n8.x4.shared.b16 {%0,%1,%2,%3}, [%4];"
        : "=r"(r[0]), "=r"(r[1]), "=r"(r[2]), "=r"(r[3]) : "r"(a));
}
__device__ __forceinline__ void mma16816(float c[4], const uint32_t a[4], const uint32_t b[2]) {
    asm volatile("mma.sync.aligned.m16n8k16.row.col.f32.f16.f16.f32 "
        "{%0,%1,%2,%3}, {%4,%5,%6,%7}, {%8,%9}, {%0,%1,%2,%3};"
        : "+f"(c[0]), "+f"(c[1]), "+f"(c[2]), "+f"(c[3])
        : "r"(a[0]), "r"(a[1]), "r"(a[2]), "r"(a[3]), "r"(b[0]), "r"(b[1]));
}
__device__ __forceinline__ void cpa16(uint32_t dst, const void* src) {
    asm volatile("cp.async.cg.shared.global [%0], [%1], 16;" :: "r"(dst), "l"(src));
}
#define CP_COMMIT() asm volatile("cp.async.commit_group;" ::: "memory")
#define CP_WAIT0()  asm volatile("cp.async.wait_group 0;" ::: "memory")
#define CP_WAIT1()  asm volatile("cp.async.wait_group 1;" ::: "memory")

// smem stage layout (bytes), padded stride 72 fp16 = 144B (conflict-free ldmatrix)
// CTA tile 128m x 128n: A 128*144 + B 128*144 per stage
constexpr int B_OFF = 18432;
constexpr int STGSZ = 36864;
constexpr int NSTG  = 3;
constexpr int DSMEM = NSTG * STGSZ;    // 110592 B -> 2 CTAs/SM

// ---------------- mean / rstd (float4 loads) ----------------
__global__ void k_meanvar(const float* __restrict__ x, int which) {
    int row = blockIdx.x;
    const float4* p = (const float4*)(x + (size_t)row * 768);
    float s = 0.f, ss = 0.f;
    for (int t = threadIdx.x; t < 192; t += 256) {
        float4 v = p[t];
        s += v.x + v.y + v.z + v.w;
        ss = fmaf(v.x, v.x, ss); ss = fmaf(v.y, v.y, ss);
        ss = fmaf(v.z, v.z, ss); ss = fmaf(v.w, v.w, ss);
    }
    #pragma unroll
    for (int o = 16; o; o >>= 1) {
        s  += __shfl_xor_sync(0xffffffffu, s, o);
        ss += __shfl_xor_sync(0xffffffffu, ss, o);
    }
    __shared__ float sm[8], sm2[8];
    int w = threadIdx.x >> 5;
    if ((threadIdx.x & 31) == 0) { sm[w] = s; sm2[w] = ss; }
    __syncthreads();
    if (threadIdx.x == 0) {
        float S = 0.f, SS = 0.f;
        #pragma unroll
        for (int q = 0; q < 8; ++q) { S += sm[q]; SS += sm2[q]; }
        float mean = S * (1.f / 768.f);
        float var  = SS * (1.f / 768.f) - mean * mean;
        float d    = var + 1e-12f;
        float r    = 1.f / (d * d);            // faithful: std = (var+eps)^2
        if (which == 0) { g_mean_rel[row] = mean; g_rstd_rel[row] = r; }
        else            { g_mean_ent[row] = mean; g_rstd_ent[row] = r; }
    }
}

// ---------------- transpose params ----------------
__global__ void k_transpose4(const float* __restrict__ ea, const float* __restrict__ eb,
                             const float* __restrict__ ra, const float* __restrict__ rb) {
    int which = blockIdx.y;
    const float* in = (which == 0) ? ea : (which == 1) ? eb : (which == 2) ? ra : rb;
    float* out = (which == 0) ? g_alT : (which == 1) ? g_beT : (which == 2) ? g_ralT : g_rbeT;
    int idx = blockIdx.x * 256 + threadIdx.x;
    if (idx < Mv * 768) {
        int j = idx / 768;
        int e = idx - j * 768;
        out[idx] = in[e * Mv + j];
    }
}

// ---------------- convert weights to fp16 ----------------
__global__ void k_cvtw(const float* __restrict__ egWb, const float* __restrict__ egWg,
                       const float* __restrict__ rgWb, const float* __restrict__ rgWg) {
    int idx = blockIdx.x * 256 + threadIdx.x;
    if (idx >= 1536 * 768) return;
    int which = blockIdx.y;
    int row = idx / 768, col = idx - row * 768;
    const float* Wb = which ? rgWb : egWb;
    const float* Wg = which ? rgWg : egWg;
    float x = (row < 768) ? Wb[row * 768 + col] : Wg[(row - 768) * 768 + col];
    __half h = __float2half_rn(x);
    if (which) g_W2h[idx] = h;
    else       g_W1h[idx] = h;
}

// ---------------- erow / ecol ----------------
__global__ void k_rowcol_ent(const float* __restrict__ eh, const int* __restrict__ mir) {
    int b = blockIdx.x >> 7, i = blockIdx.x & 127;
    __shared__ int mids[Mv];
    if (threadIdx.x < Mv) mids[threadIdx.x] = mir[i * Mv + threadIdx.x];
    __syncthreads();
    for (int e = threadIdx.x; e < Ev; e += 256) {
        float aR = 0.f, aC = 0.f;
        #pragma unroll 4
        for (int j = 0; j < Mv; ++j) {
            float v = eh[((size_t)b * Sv + mids[j]) * Ev + e];
            aR = fmaf(v, g_alT[j * Ev + e], aR);
            aC = fmaf(v, g_beT[j * Ev + e], aC);
        }
        g_erow[((size_t)b * Mv + i) * Ev + e] = aR;     // [b][i][e]
        g_ecol[((size_t)b * Ev + e) * Mv + i] = aC;     // [b][e][j]
    }
}

// ---------------- materialize ent_ctx fp16: g_A1[byi][j][e] ----------------
__global__ void k_actx() {
    int byi = blockIdx.x;              // b*128 + i
    int b = byi >> 7;
    __shared__ float er[768];
    __shared__ float S[32][129];
    int tid = threadIdx.x;
    #pragma unroll
    for (int q = 0; q < 3; ++q) er[q * 256 + tid] = g_erow[(size_t)byi * Ev + q * 256 + tid];
    for (int t = 0; t < 24; ++t) {
        int e0 = t * 32;
        __syncthreads();
        #pragma unroll
        for (int q = 0; q < 16; ++q) {
            int idx = q * 256 + tid;
            int e = idx >> 7, j = idx & 127;
            S[e][j] = g_ecol[((size_t)b * Ev + e0 + e) * Mv + j];
        }
        __syncthreads();
        int j = tid >> 1, h = tid & 1;
        uint32_t hh[8];
        #pragma unroll
        for (int p = 0; p < 8; ++p) {
            int e = h * 16 + p * 2;
            float x0 = er[e0 + e]     * S[e][j];
            float x1 = er[e0 + e + 1] * S[e + 1][j];
            __half2 v = __float22half2_rn(make_float2(x0, x1));
            hh[p] = *(uint32_t*)&v;
        }
        __half* dst = g_A1 + ((size_t)byi * 128 + j) * 768 + e0 + h * 16;
        *(uint4*)(dst)     = make_uint4(hh[0], hh[1], hh[2], hh[3]);
        *(uint4*)(dst + 8) = make_uint4(hh[4], hh[5], hh[6], hh[7]);
    }
}

// ---------------- rrow / rcol from rel_guided ----------------
__global__ void k_rowcol_rel(const float* __restrict__ rg) {
    int b = blockIdx.x >> 7, k = blockIdx.x & 127;
    const float* rgb = rg + (size_t)b * Mv * Mv * Rv;
    for (int r = threadIdx.x; r < Rv; r += 256) {
        float aR = 0.f, aC = 0.f;
        const float* prow = rgb + (size_t)k * Mv * Rv + r;
        const float* pcol = rgb + (size_t)k * Rv + r;
        #pragma unroll 4
        for (int j = 0; j < Mv; ++j) {
            aR = fmaf(prow[(size_t)j * Rv], g_ralT[j * Rv + r], aR);
            aC = fmaf(pcol[(size_t)j * Mv * Rv], g_rbeT[j * Rv + r], aC);
        }
        g_rrow[(b * Rv + r) * Mv + k] = aR;
        g_rcol[(b * Rv + r) * Mv + k] = aC;
    }
}

// ---------------- cond[(b,s)][r] -> fp16 ----------------
__global__ void k_cond2(const float* __restrict__ lam, const int* __restrict__ upper) {
    int b = blockIdx.y;
    int s0 = blockIdx.x * 128;
    __shared__ float rrS[32][128], rcS[32][128], lamS[32];
    __shared__ int iS[128], jS[128];
    int tid = threadIdx.x;
    if (tid < 128) {
        int s = s0 + tid;
        if (s < Sv) { int u = upper[s]; iS[tid] = u >> 7; jS[tid] = u & 127; }
        else        { iS[tid] = 0; jS[tid] = 0; }
    }
    int s_loc = tid >> 1, rh = (tid & 1) * 16;
    int s = s0 + s_loc;
    for (int rch = 0; rch < 24; ++rch) {
        int r0 = rch * 32;
        __syncthreads();
        #pragma unroll
        for (int q = 0; q < 16; ++q) {
            int idx = q * 256 + tid;
            int rk = idx >> 7, mm = idx & 127;
            rrS[rk][mm] = g_rrow[((size_t)b * Rv + r0 + rk) * Mv + mm];
            rcS[rk][mm] = g_rcol[((size_t)b * Rv + r0 + rk) * Mv + mm];
        }
        if (tid < 32) lamS[tid] = lam[r0 + tid];
        __syncthreads();
        if (s < Sv) {
            int ii = iS[s_loc], jj = jS[s_loc];
            uint32_t h8[8];
            #pragma unroll
            for (int p = 0; p < 8; ++p) {
                int r = rh + p * 2;
                float l0 = lamS[r], l1 = lamS[r + 1];
                float x0 = l0 * rrS[r][ii] * rcS[r][jj] + (1.f - l0) * rrS[r][jj] * rcS[r][ii];
                float x1 = l1 * rrS[r + 1][ii] * rcS[r + 1][jj] + (1.f - l1) * rrS[r + 1][jj] * rcS[r + 1][ii];
                __half2 h = __float22half2_rn(make_float2(x0, x1));
                h8[p] = *(uint32_t*)&h;
            }
            size_t off = ((size_t)b * Sv + s) * Rv + r0 + rh;
            *(uint4*)(g_cDh + off)     = make_uint4(h8[0], h8[1], h8[2], h8[3]);
            *(uint4*)(g_cDh + off + 8) = make_uint4(h8[4], h8[5], h8[6], h8[7]);
        }
    }
}

// ================= generic fp16 GEMM + CLN body (256 thr, 2 CTA/SM, 3-stage) =================
// CTA m=128 x n=128 (64 out-cols x {Wb,Wg} interleaved); 8 warps, warp tile 32x64.
template <typename StageF>
__device__ __forceinline__ void gemm_body(
    char* base, uint32_t sm0, int tid, int w, int L,
    StageF stage,
    const float* x_src, float* x_dst, size_t row_base, int col0,
    const float* mS, const float* sS, const float* betS, const float* gamS) {
    const int m0w = (w >> 1) * 32, n0w = (w & 1) * 64;

    float acc[2][8][4];
    #pragma unroll
    for (int mt = 0; mt < 2; ++mt)
        #pragma unroll
        for (int nt = 0; nt < 8; ++nt)
            #pragma unroll
            for (int q = 0; q < 4; ++q) acc[mt][nt][q] = 0.f;

    const uint32_t aBase = sm0 + (uint32_t)(m0w + (L & 15)) * 144 + (uint32_t)(L >> 4) * 16;
    const uint32_t bBase = sm0 + B_OFF
        + (uint32_t)(n0w + (L & 7) + ((L >> 4) << 3)) * 144 + (uint32_t)((L >> 3) & 1) * 16;

    stage(0, 0); CP_COMMIT();
    stage(1, 1); CP_COMMIT();

    int st_nxt = 2;
    for (int ch = 0; ch < 12; ++ch) {
        if (ch >= 10) { CP_WAIT0(); } else { CP_WAIT1(); }
        __syncthreads();
        if (ch < 10) {
            stage(ch + 2, st_nxt);
            CP_COMMIT();
            if (++st_nxt == NSTG) st_nxt = 0;
        } else if (ch == 11) {
            // prefetch epilogue x tile [128 rows x 64 cols] into stage0 (free now), stride 272B
            const float* src = x_src + row_base * 768 + col0;
            #pragma unroll
            for (int q = 0; q < 8; ++q) {
                int u = q * 256 + tid;
                int j = u >> 4, sg = u & 15;
                cpa16(sm0 + (uint32_t)j * 272 + sg * 16, src + (size_t)j * 768 + sg * 4);
            }
            CP_COMMIT();
        }
        const uint32_t off = (uint32_t)((ch % NSTG) * STGSZ);
        const uint32_t aA = aBase + off, bA = bBase + off;
        #pragma unroll
        for (int ks = 0; ks < 64; ks += 16) {
            uint32_t ah[2][4];
            #pragma unroll
            for (int mt = 0; mt < 2; ++mt)
                ldsm_x4(ah[mt], aA + mt * 2304 + ks * 2);
            #pragma unroll
            for (int np = 0; np < 4; ++np) {
                uint32_t bh[4];
                ldsm_x4(bh, bA + np * 2304 + ks * 2);
                #pragma unroll
                for (int mt = 0; mt < 2; ++mt) {
                    mma16816(acc[mt][2 * np],     ah[mt], bh);
                    mma16816(acc[mt][2 * np + 1], ah[mt], bh + 2);
                }
            }
        }
    }

    // ---- epilogue: x tile already in smem (stage0), transform in place, store coalesced ----
    CP_WAIT0();
    __syncthreads();
    float* XS = (float*)base;                       // [128][68]
    const int gid = L >> 2, tig = L & 3;
    #pragma unroll
    for (int mt = 0; mt < 2; ++mt) {
        int j1 = m0w + mt * 16 + gid, j2 = j1 + 8;
        float mn1 = mS[j1], rs1 = sS[j1], mn2 = mS[j2], rs2 = sS[j2];
        #pragma unroll
        for (int nt = 0; nt < 8; ++nt) {
            int rl = (n0w >> 1) + nt * 4 + tig;
            const float* c = acc[mt][nt];
            float x1 = XS[j1 * 68 + rl], x2 = XS[j2 * 68 + rl];
            XS[j1 * 68 + rl] = (x1 - mn1) * rs1 * (c[1] + gamS[rl]) + c[0] + betS[rl];
            XS[j2 * 68 + rl] = (x2 - mn2) * rs2 * (c[3] + gamS[rl]) + c[2] + betS[rl];
        }
    }
    __syncthreads();
    {
        float* dst = x_dst + row_base * 768 + col0;
        int j = tid >> 1, c0 = (tid & 1) * 32;
        #pragma unroll
        for (int q = 0; q < 8; ++q)
            *(float4*)(dst + (size_t)j * 768 + c0 + q * 4) = *(const float4*)(XS + j * 68 + c0 + q * 4);
    }
}

// ================= GEMM1 -> rel_guided =================
__global__ __launch_bounds__(256, 2) void k_gemm1(
    const float* __restrict__ rel_hs, float* __restrict__ rel_out,
    const float* __restrict__ ebeta, const float* __restrict__ egam) {
    extern __shared__ char base[];
    const uint32_t sm0 = s2u(base);
    const int tid = threadIdx.x, w = tid >> 5, L = tid & 31;
    const int r0 = blockIdx.x * 64;            // 12 n-tiles of 64 r
    const int byi = blockIdx.y;

    __shared__ float betS[64], gamS[64], mS[128], sS[128];
    if (tid < 64) { betS[tid] = ebeta[r0 + tid]; gamS[tid] = egam[r0 + tid]; }
    if (tid < 128) {
        mS[tid] = g_mean_rel[byi * 128 + tid];
        sS[tid] = g_rstd_rel[byi * 128 + tid];
    }

    const int cRow = tid >> 3, cSeg = tid & 7;
    auto stage = [&](int ch, int st) {
        const int k0 = ch * 64;
        uint32_t s = sm0 + (uint32_t)(st * STGSZ);
        #pragma unroll
        for (int q = 0; q < 4; ++q) {
            int row = cRow + q * 32;
            cpa16(s + (uint32_t)row * 144 + cSeg * 16,
                  g_A1 + ((size_t)byi * 128 + row) * 768 + k0 + cSeg * 8);
            int src = r0 + (row >> 1) + (row & 1) * 768;
            cpa16(s + B_OFF + (uint32_t)row * 144 + cSeg * 16,
                  g_W1h + (size_t)src * 768 + k0 + cSeg * 8);
        }
    };

    gemm_body(base, sm0, tid, w, L, stage,
              rel_hs, rel_out, (size_t)byi * 128, r0, mS, sS, betS, gamS);
}

// ================= GEMM2 -> ent_guided =================
__global__ __launch_bounds__(256, 2) void k_gemm2(
    const float* __restrict__ ent_hs, float* __restrict__ ent_out,
    const float* __restrict__ rbeta, const float* __restrict__ rgam) {
    extern __shared__ char base[];
    const uint32_t sm0 = s2u(base);
    const int tid = threadIdx.x, w = tid >> 5, L = tid & 31;
    const int e0 = blockIdx.x * 64;            // 12 n-tiles of 64 e
    const int m0 = blockIdx.y * 128;

    __shared__ float betS[64], gamS[64], mS[128], sS[128];
    if (tid < 64) { betS[tid] = rbeta[e0 + tid]; gamS[tid] = rgam[e0 + tid]; }
    if (tid < 128) {
        mS[tid] = g_mean_ent[m0 + tid];
        sS[tid] = g_rstd_ent[m0 + tid];
    }

    const int cRow = tid >> 3, cSeg = tid & 7;
    auto stage = [&](int ch, int st) {
        const int k0 = ch * 64;
        uint32_t s = sm0 + (uint32_t)(st * STGSZ);
        #pragma unroll
        for (int q = 0; q < 4; ++q) {
            int row = cRow + q * 32;
            cpa16(s + (uint32_t)row * 144 + cSeg * 16,
                  g_cDh + (size_t)(m0 + row) * Rv + k0 + cSeg * 8);
            int src = e0 + (row >> 1) + (row & 1) * 768;
            cpa16(s + B_OFF + (uint32_t)row * 144 + cSeg * 16,
                  g_W2h + (size_t)src * 768 + k0 + cSeg * 8);
        }
    };

    gemm_body(base, sm0, tid, w, L, stage,
              ent_hs, ent_out, (size_t)m0, e0, mS, sS, betS, gamS);
}

// ---------------- launch ----------------
extern "C" void kernel_launch(void* const* d_in, const int* in_sizes, int n_in,
                              void* d_out, int out_size) {
    const float* ent_hs    = (const float*)d_in[0];
    const float* rel_hs    = (const float*)d_in[1];
    const float* ent_alpha = (const float*)d_in[2];
    const float* ent_beta  = (const float*)d_in[3];
    const float* rel_alpha = (const float*)d_in[4];
    const float* rel_beta  = (const float*)d_in[5];
    const float* lam       = (const float*)d_in[6];
    const float* egr_Wb    = (const float*)d_in[7];
    const float* egr_Wg    = (const float*)d_in[8];
    const float* egr_beta  = (const float*)d_in[9];
    const float* egr_gamma = (const float*)d_in[10];
    const float* rge_Wb    = (const float*)d_in[11];
    const float* rge_Wg    = (const float*)d_in[12];
    const float* rge_beta  = (const float*)d_in[13];
    const float* rge_gamma = (const float*)d_in[14];
    const int*   mirror    = (const int*)d_in[15];
    const int*   upper     = (const int*)d_in[16];

    float* ent_out = (float*)d_out;                              // [B,S,E]
    float* rel_out = (float*)d_out + (size_t)Bc * Sv * Ev;       // [B,M,M,R]

    cudaFuncSetAttribute(k_gemm1, cudaFuncAttributeMaxDynamicSharedMemorySize, DSMEM);
    cudaFuncSetAttribute(k_gemm2, cudaFuncAttributeMaxDynamicSharedMemorySize, DSMEM);

    k_meanvar<<<Bc * Mv * Mv, 256>>>(rel_hs, 0);
    k_meanvar<<<BSv, 256>>>(ent_hs, 1);
    k_transpose4<<<dim3((Mv * 768 + 255) / 256, 4), 256>>>(ent_alpha, ent_beta, rel_alpha, rel_beta);
    k_cvtw<<<dim3((1536 * 768 + 255) / 256, 2), 256>>>(egr_Wb, egr_Wg, rge_Wb, rge_Wg);
    k_rowcol_ent<<<Bc * Mv, 256>>>(ent_hs, mirror);
    k_actx<<<Bc * Mv, 256>>>();
    k_gemm1<<<dim3(12, Bc * Mv), 256, DSMEM>>>(rel_hs, rel_out, egr_beta, egr_gamma);
    k_rowcol_rel<<<Bc * Mv, 256>>>(rel_out);
    k_cond2<<<dim3((Sv + 127) / 128, Bc), 256>>>(lam, upper);
    k_gemm2<<<dim3(12, (BSv + 127) / 128), 256, DSMEM>>>(ent_hs, ent_out, rge_beta, rge_gamma);
}